// round 1
// baseline (speedup 1.0000x reference)
#include <cuda_runtime.h>
#include <math.h>

#define SPAT 32768           // D*H*W
#define CCH  256             // channels
#define REG_SZ (2*256*32768) // one region (b, 256, 32768)

// ---------------- scratch (device globals; no allocations allowed) ----------
__device__ float g_q[REG_SZ];
__device__ float g_k[REG_SZ];
__device__ float g_v[REG_SZ];
__device__ float g_pool[2 * 512 * 3];   // [region][b*256+c][max,avg,min]
__device__ float g_gate[2 * 512];       // [region][b*256+c]

// ---------------- QKV GEMM: q/k/v = W @ x + b ------------------------------
// Per (mat, batch): C[256, 32768] = W[256,256] @ X[256,32768]; classic
// 128x128x8 SGEMM, 256 threads, 8x8 microtile.
__global__ __launch_bounds__(256)
void qkv_gemm(const float* __restrict__ x,
              const float* __restrict__ Wq, const float* __restrict__ bq,
              const float* __restrict__ Wk, const float* __restrict__ bk,
              const float* __restrict__ Wv, const float* __restrict__ bv)
{
    __shared__ float As[8][128];
    __shared__ float Bs[8][128];

    int z   = blockIdx.z;
    int mat = z >> 1, b = z & 1;
    const float* W    = (mat == 0) ? Wq : ((mat == 1) ? Wk : Wv);
    const float* bias = (mat == 0) ? bq : ((mat == 1) ? bk : bv);
    float* out        = ((mat == 0) ? g_q : ((mat == 1) ? g_k : g_v)) + (size_t)b * CCH * SPAT;
    const float* X    = x + (size_t)b * CCH * SPAT;

    int tid = threadIdx.x;
    int m0 = blockIdx.y * 128;
    int n0 = blockIdx.x * 128;
    int tx = tid & 15, ty = tid >> 4;

    int a_row = tid >> 1;          // 0..127
    int a_col = (tid & 1) * 4;     // 0 / 4
    int b_row = tid >> 5;          // 0..7
    int b_col = (tid & 31) * 4;    // 0..124

    float acc[8][8];
#pragma unroll
    for (int i = 0; i < 8; i++)
#pragma unroll
        for (int j = 0; j < 8; j++) acc[i][j] = 0.f;

    for (int k0 = 0; k0 < 256; k0 += 8) {
        float4 av  = *(const float4*)&W[(m0 + a_row) * 256 + k0 + a_col];
        float4 bv4 = *(const float4*)&X[(size_t)(k0 + b_row) * SPAT + n0 + b_col];
        As[a_col + 0][a_row] = av.x;
        As[a_col + 1][a_row] = av.y;
        As[a_col + 2][a_row] = av.z;
        As[a_col + 3][a_row] = av.w;
        *(float4*)&Bs[b_row][b_col] = bv4;
        __syncthreads();
#pragma unroll
        for (int kk = 0; kk < 8; kk++) {
            float af[8], bf[8];
#pragma unroll
            for (int i = 0; i < 8; i++) af[i] = As[kk][ty * 8 + i];
#pragma unroll
            for (int j = 0; j < 8; j++) bf[j] = Bs[kk][tx * 8 + j];
#pragma unroll
            for (int i = 0; i < 8; i++)
#pragma unroll
                for (int j = 0; j < 8; j++) acc[i][j] += af[i] * bf[j];
        }
        __syncthreads();
    }

#pragma unroll
    for (int i = 0; i < 8; i++) {
        int row = m0 + ty * 8 + i;
        float bb = bias[row];
        float* op = out + (size_t)row * SPAT + n0 + tx * 8;
        float4 v0 = make_float4(acc[i][0] + bb, acc[i][1] + bb, acc[i][2] + bb, acc[i][3] + bb);
        float4 v1 = make_float4(acc[i][4] + bb, acc[i][5] + bb, acc[i][6] + bb, acc[i][7] + bb);
        *(float4*)op       = v0;
        *(float4*)(op + 4) = v1;
    }
}

// ---------------- fused branch: softmax-attn * v -> SE -> out_s, + sup prior
__global__ __launch_bounds__(256)
void branch_kernel(int ch_off,
                   const float* __restrict__ w1,   const float* __restrict__ b1,
                   const float* __restrict__ w2,   const float* __restrict__ b2,
                   const float* __restrict__ wsup, const float* __restrict__ bsup, int nsup,
                   float* __restrict__ out_s, float* __restrict__ sup_out)
{
    __shared__ float w1s[16 * 128];
    __shared__ float w2s[256 * 16];
    __shared__ float wss[6 * 128];
    __shared__ float b1s[16];
    __shared__ float b2s[256];
    __shared__ float bss[6];

    int tid = threadIdx.x;
    for (int i = tid; i < 2048; i += 256) w1s[i] = w1[i];
    for (int i = tid; i < 4096; i += 256) w2s[i] = w2[i];
    for (int i = tid; i < nsup * 128; i += 256) wss[i] = wsup[i];
    if (tid < 16)   b1s[tid] = b1[tid];
    if (tid < nsup) bss[tid] = bsup[tid];
    b2s[tid] = b2[tid];
    __syncthreads();

    int vg = blockIdx.x * 256 + tid;   // global voxel (b,s), < 65536
    int b  = vg >> 15;
    int s  = vg & (SPAT - 1);
    size_t base = (size_t)b * CCH * SPAT + (size_t)ch_off * SPAT + s;

    float tacc[16];
#pragma unroll
    for (int j = 0; j < 16; j++) tacc[j] = 0.f;
    float supacc[6] = {0.f, 0.f, 0.f, 0.f, 0.f, 0.f};

#pragma unroll 1
    for (int h = 0; h < 8; h++) {
        float qv[16], ev[16], vv[16];
#pragma unroll
        for (int i = 0; i < 16; i++) {
            size_t a = base + (size_t)(h * 16 + i) * SPAT;
            qv[i] = g_q[a];
            float kv = g_k[a];
            vv[i] = g_v[a];
            ev[i] = qv[i] * kv * 0.25f;   // SCALE = HD^-0.5 = 0.25
        }
        float m = ev[0];
#pragma unroll
        for (int i = 1; i < 16; i++) m = fmaxf(m, ev[i]);
        float ssum = 0.f;
#pragma unroll
        for (int i = 0; i < 16; i++) { ev[i] = __expf(ev[i] - m); ssum += ev[i]; }
        float inv = 1.f / ssum;
#pragma unroll
        for (int i = 0; i < 16; i++) {
            float o = ev[i] * inv * vv[i];
            int c = h * 16 + i;
#pragma unroll
            for (int j = 0; j < 16; j++) tacc[j] += w1s[j * 128 + c] * o;
            for (int j = 0; j < nsup; j++) supacc[j] += wss[j * 128 + c] * qv[i];
        }
    }
#pragma unroll
    for (int j = 0; j < 16; j++) tacc[j] = fmaxf(tacc[j] + b1s[j], 0.f);

    size_t obase = (size_t)b * CCH * SPAT + s;
#pragma unroll 4
    for (int o = 0; o < 256; o++) {
        float a = b2s[o];
#pragma unroll
        for (int j = 0; j < 16; j++) a += w2s[o * 16 + j] * tacc[j];
        out_s[obase + (size_t)o * SPAT] = 1.f / (1.f + __expf(-a));
    }
    size_t sbase = (size_t)b * nsup * SPAT + s;
    for (int j = 0; j < nsup; j++)
        sup_out[sbase + (size_t)j * SPAT] = supacc[j] + bss[j];
}

// ---------------- deterministic max/mean/min pooling ------------------------
__global__ __launch_bounds__(256)
void pool_kernel(const float* __restrict__ outbase)
{
    __shared__ float smx[256], smn[256], ssm[256];
    int blk = blockIdx.x;        // 0..1023 : region*512 + b*256 + c
    int r   = blk >> 9;
    int bc  = blk & 511;
    const float* p = outbase + (size_t)r * REG_SZ + (size_t)bc * SPAT;
    int tid = threadIdx.x;
    float mx = -1e30f, mn = 1e30f, sm = 0.f;
    for (int i = tid; i < SPAT; i += 256) {
        float v = p[i];
        mx = fmaxf(mx, v); mn = fminf(mn, v); sm += v;
    }
    smx[tid] = mx; smn[tid] = mn; ssm[tid] = sm;
    __syncthreads();
    for (int st = 128; st > 0; st >>= 1) {
        if (tid < st) {
            smx[tid] = fmaxf(smx[tid], smx[tid + st]);
            smn[tid] = fminf(smn[tid], smn[tid + st]);
            ssm[tid] += ssm[tid + st];
        }
        __syncthreads();
    }
    if (tid == 0) {
        g_pool[blk * 3 + 0] = smx[0];
        g_pool[blk * 3 + 1] = ssm[0] * (1.f / 32768.f);
        g_pool[blk * 3 + 2] = smn[0];
    }
}

// ---------------- gate: Conv1d(3->1) + FC squeeze-excite --------------------
__global__ __launch_bounds__(256)
void gate_kernel(const float* __restrict__ sq1w, const float* __restrict__ sq1b,
                 const float* __restrict__ sq2w, const float* __restrict__ sq2b,
                 const float* __restrict__ f1w1, const float* __restrict__ f1b1,
                 const float* __restrict__ f1w2, const float* __restrict__ f1b2,
                 const float* __restrict__ f2w1, const float* __restrict__ f2b1,
                 const float* __restrict__ f2w2, const float* __restrict__ f2b2)
{
    int r = blockIdx.x >> 1, b = blockIdx.x & 1;
    const float* sqw = r ? sq2w : sq1w;
    const float* sqb = r ? sq2b : sq1b;
    const float* fw1 = r ? f2w1 : f1w1;
    const float* fb1 = r ? f2b1 : f1b1;
    const float* fw2 = r ? f2w2 : f1w2;
    const float* fb2 = r ? f2b2 : f1b2;

    __shared__ float sqs[256], hs[16];
    int c = threadIdx.x;
    const float* pr = &g_pool[(r * 512 + b * 256 + c) * 3];
    sqs[c] = pr[0] * sqw[0] + pr[1] * sqw[1] + pr[2] * sqw[2] + sqb[0];
    __syncthreads();
    if (c < 16) {
        float a = fb1[c];
        for (int j = 0; j < 256; j++) a += fw1[c * 256 + j] * sqs[j];
        hs[c] = fmaxf(a, 0.f);
    }
    __syncthreads();
    float a = fb2[c];
#pragma unroll
    for (int j = 0; j < 16; j++) a += fw2[c * 16 + j] * hs[j];
    g_gate[r * 512 + b * 256 + c] = 1.f / (1.f + __expf(-a));
}

// ---------------- apply gate in place on out1|out2 --------------------------
__global__ __launch_bounds__(256)
void scale_kernel(float* __restrict__ out)
{
    size_t i = (size_t)blockIdx.x * 256 + threadIdx.x;  // float4 index, < 8388608
    int r  = (int)(i >> 22);            // 4194304 float4 per region
    int bc = (int)((i >> 13) & 511);    // 8192 float4 per (b,c) row
    float g = g_gate[r * 512 + bc];
    float4* p = ((float4*)out) + i;
    float4 v = *p;
    v.x *= g; v.y *= g; v.z *= g; v.w *= g;
    *p = v;
}

// ---------------- launch ----------------------------------------------------
extern "C" void kernel_launch(void* const* d_in, const int* in_sizes, int n_in,
                              void* d_out, int out_size)
{
    const float* x      = (const float*)d_in[0];
    const float* Wq     = (const float*)d_in[1];
    const float* bq     = (const float*)d_in[2];
    const float* Wk     = (const float*)d_in[3];
    const float* bk     = (const float*)d_in[4];
    const float* Wv     = (const float*)d_in[5];
    const float* bv     = (const float*)d_in[6];
    const float* Wq1p   = (const float*)d_in[7];
    const float* bq1p   = (const float*)d_in[8];
    const float* Wq2p   = (const float*)d_in[9];
    const float* bq2p   = (const float*)d_in[10];
    const float* sq1_w  = (const float*)d_in[11];
    const float* sq1_b  = (const float*)d_in[12];
    const float* sq2_w  = (const float*)d_in[13];
    const float* sq2_b  = (const float*)d_in[14];
    const float* se1_w1 = (const float*)d_in[15];
    const float* se1_b1 = (const float*)d_in[16];
    const float* se1_w2 = (const float*)d_in[17];
    const float* se1_b2 = (const float*)d_in[18];
    const float* se2_w1 = (const float*)d_in[19];
    const float* se2_b1 = (const float*)d_in[20];
    const float* se2_w2 = (const float*)d_in[21];
    const float* se2_b2 = (const float*)d_in[22];
    const float* sec1_w1 = (const float*)d_in[23];
    const float* sec1_b1 = (const float*)d_in[24];
    const float* sec1_w2 = (const float*)d_in[25];
    const float* sec1_b2 = (const float*)d_in[26];
    const float* sec2_w1 = (const float*)d_in[27];
    const float* sec2_b1 = (const float*)d_in[28];
    const float* sec2_w2 = (const float*)d_in[29];
    const float* sec2_b2 = (const float*)d_in[30];

    float* out  = (float*)d_out;
    float* out1 = out;
    float* out2 = out + (size_t)REG_SZ;            // 16777216
    float* sup1 = out + (size_t)2 * REG_SZ;        // 33554432
    float* sup2 = sup1 + 2 * 6 * SPAT;             // 33947648

    dim3 gg(256, 2, 6);   // 256 n-tiles, 2 m-tiles, (3 mats x 2 batches)
    qkv_gemm<<<gg, 256>>>(x, Wq, bq, Wk, bk, Wv, bv);

    branch_kernel<<<256, 256>>>(0,   se1_w1, se1_b1, se1_w2, se1_b2,
                                Wq1p, bq1p, 6, out1, sup1);
    branch_kernel<<<256, 256>>>(128, se2_w1, se2_b1, se2_w2, se2_b2,
                                Wq2p, bq2p, 1, out2, sup2);

    pool_kernel<<<1024, 256>>>(out);

    gate_kernel<<<4, 256>>>(sq1_w, sq1_b, sq2_w, sq2_b,
                            sec1_w1, sec1_b1, sec1_w2, sec1_b2,
                            sec2_w1, sec2_b1, sec2_w2, sec2_b2);

    scale_kernel<<<32768, 256>>>(out);
}

// round 3
// speedup vs baseline: 1.5599x; 1.5599x over previous
#include <cuda_runtime.h>
#include <cuda_bf16.h>
#include <math.h>
#include <stdint.h>

#define SPAT 32768           // D*H*W
#define CCH  256             // channels
#define REG_SZ (2*256*32768) // one region (b, 256, 32768)

// ---------------- scratch (device globals; no allocations allowed) ----------
__device__ float g_q[REG_SZ];
__device__ float g_k[REG_SZ];
__device__ float g_v[REG_SZ];
__device__ float g_pool[2 * 512 * 3];   // [region][b*256+c][max,avg,min]
__device__ float g_gate[2 * 512];       // [region][b*256+c]

// ======================= helpers ============================================
__device__ __forceinline__ uint32_t smem_u32(const void* p) {
    uint32_t a;
    asm("{ .reg .u64 t; cvta.to.shared.u64 t, %1; cvt.u32.u64 %0, t; }"
        : "=r"(a) : "l"(p));
    return a;
}

__device__ __forceinline__ void ldm_x4(uint32_t* r, uint32_t a) {
    asm volatile("ldmatrix.sync.aligned.m8n8.x4.shared.b16 {%0,%1,%2,%3}, [%4];"
        : "=r"(r[0]), "=r"(r[1]), "=r"(r[2]), "=r"(r[3]) : "r"(a));
}
__device__ __forceinline__ void ldm_x4t(uint32_t* r, uint32_t a) {
    asm volatile("ldmatrix.sync.aligned.m8n8.x4.trans.shared.b16 {%0,%1,%2,%3}, [%4];"
        : "=r"(r[0]), "=r"(r[1]), "=r"(r[2]), "=r"(r[3]) : "r"(a));
}
__device__ __forceinline__ void mma_bf16(float* c, const uint32_t* a, const uint32_t* b) {
    asm volatile(
        "mma.sync.aligned.m16n8k16.row.col.f32.bf16.bf16.f32 "
        "{%0,%1,%2,%3}, {%4,%5,%6,%7}, {%8,%9}, {%0,%1,%2,%3};"
        : "+f"(c[0]), "+f"(c[1]), "+f"(c[2]), "+f"(c[3])
        : "r"(a[0]), "r"(a[1]), "r"(a[2]), "r"(a[3]), "r"(b[0]), "r"(b[1]));
}

// float4 -> bf16 hi pair-words + lo pair-words
__device__ __forceinline__ void split4(float4 v, uint32_t& h0, uint32_t& h1,
                                       uint32_t& l0, uint32_t& l1) {
    __nv_bfloat16 hx = __float2bfloat16_rn(v.x), hy = __float2bfloat16_rn(v.y);
    __nv_bfloat16 hz = __float2bfloat16_rn(v.z), hw = __float2bfloat16_rn(v.w);
    __nv_bfloat16 lx = __float2bfloat16_rn(v.x - __bfloat162float(hx));
    __nv_bfloat16 ly = __float2bfloat16_rn(v.y - __bfloat162float(hy));
    __nv_bfloat16 lz = __float2bfloat16_rn(v.z - __bfloat162float(hz));
    __nv_bfloat16 lw = __float2bfloat16_rn(v.w - __bfloat162float(hw));
    h0 = (uint32_t)__bfloat16_as_ushort(hx) | ((uint32_t)__bfloat16_as_ushort(hy) << 16);
    h1 = (uint32_t)__bfloat16_as_ushort(hz) | ((uint32_t)__bfloat16_as_ushort(hw) << 16);
    l0 = (uint32_t)__bfloat16_as_ushort(lx) | ((uint32_t)__bfloat16_as_ushort(ly) << 16);
    l1 = (uint32_t)__bfloat16_as_ushort(lz) | ((uint32_t)__bfloat16_as_ushort(lw) << 16);
}

// ---------------- SMEM layout (per buffer, 71680 B; double buffered) --------
// A (W tile): 128 rows x 64 k bf16, row stride 144 B (padded) -> 18432 B per sel
// B (X tile): 64 rows(k) x 128 n bf16, row stride 272 B (padded) -> 17408 B per sel
#define A_STRIDE 144
#define B_STRIDE 272
#define OFF_AH 0
#define OFF_AL 18432
#define OFF_BH 36864
#define OFF_BL 54272
#define BUF_SZ 71680
#define GEMM_SMEM (2 * BUF_SZ)

// ================== mma.sync QKV GEMM: q/k/v = W @ x + b ====================
// grid: (256 ntiles, 2 mtiles, 6 = mat*2+batch); 256 threads (8 warps: 4M x 2N)
__global__ __launch_bounds__(256, 1)
void qkv_gemm_mma(const float* __restrict__ x,
                  const float* __restrict__ Wq, const float* __restrict__ bq,
                  const float* __restrict__ Wk, const float* __restrict__ bk,
                  const float* __restrict__ Wv, const float* __restrict__ bv)
{
    extern __shared__ char sm[];
    const uint32_t smb = smem_u32(sm);

    const int tid   = threadIdx.x;
    const int warp  = tid >> 5, lane = tid & 31;
    const int warpM = warp >> 1, warpN = warp & 1;
    const int n0    = blockIdx.x * 128;
    const int m0g   = blockIdx.y * 128;
    const int mat   = blockIdx.z >> 1, bb = blockIdx.z & 1;

    const float* W    = (mat == 0) ? Wq : ((mat == 1) ? Wk : Wv);
    const float* bias = (mat == 0) ? bq : ((mat == 1) ? bk : bv);
    float* outp = ((mat == 0) ? g_q : ((mat == 1) ? g_k : g_v))
                  + (size_t)bb * CCH * SPAT;
    const float* Xb = x + (size_t)bb * CCH * SPAT + n0;

    float acc[2][8][4];
#pragma unroll
    for (int i = 0; i < 2; i++)
#pragma unroll
        for (int j = 0; j < 8; j++)
#pragma unroll
            for (int c = 0; c < 4; c++) acc[i][j][c] = 0.f;

    float4 ra[8], rb[8];

    // ---- register-prefetch pipeline over 4 k-chunks of 64 -----------------
    auto load_regs = [&](int ch) {
        const int kc0 = ch << 6;
#pragma unroll
        for (int t = 0; t < 8; t++) {
            int idx = tid + t * 256;
            ra[t] = *(const float4*)&W[(m0g + (idx >> 4)) * 256 + kc0 + (idx & 15) * 4];
        }
#pragma unroll
        for (int t = 0; t < 8; t++) {
            int idx = tid + t * 256;
            rb[t] = *(const float4*)&Xb[(size_t)(kc0 + (idx >> 5)) * SPAT + (idx & 31) * 4];
        }
    };
    auto sts_regs = [&](int buf) {
        char* base = sm + buf * BUF_SZ;
#pragma unroll
        for (int t = 0; t < 8; t++) {
            int idx = tid + t * 256;
            uint32_t off = (uint32_t)(idx >> 4) * A_STRIDE + (idx & 15) * 8;
            uint32_t h0, h1, l0, l1; split4(ra[t], h0, h1, l0, l1);
            *(uint2*)(base + OFF_AH + off) = make_uint2(h0, h1);
            *(uint2*)(base + OFF_AL + off) = make_uint2(l0, l1);
        }
#pragma unroll
        for (int t = 0; t < 8; t++) {
            int idx = tid + t * 256;
            uint32_t off = (uint32_t)(idx >> 5) * B_STRIDE + (idx & 31) * 8;
            uint32_t h0, h1, l0, l1; split4(rb[t], h0, h1, l0, l1);
            *(uint2*)(base + OFF_BH + off) = make_uint2(h0, h1);
            *(uint2*)(base + OFF_BL + off) = make_uint2(l0, l1);
        }
    };

    load_regs(0);
    sts_regs(0);
    __syncthreads();

#pragma unroll 1
    for (int ch = 0; ch < 4; ch++) {
        if (ch < 3) load_regs(ch + 1);

        const uint32_t buf = smb + (ch & 1) * BUF_SZ;
        const uint32_t a_row  = (warpM * 32 + (lane & 15)) * A_STRIDE + (lane >> 4) * 16;
        const uint32_t b_col  = (warpN * 64) * 2 + (lane >> 4) * 16;
        const uint32_t b_rowl = (lane & 15) * B_STRIDE;

#pragma unroll
        for (int s = 0; s < 4; s++) {
            uint32_t afr[2][2][4];   // [mf][hi/lo]
#pragma unroll
            for (int mf = 0; mf < 2; mf++) {
                uint32_t base = buf + a_row + mf * (16 * A_STRIDE) + s * 32;
                ldm_x4(afr[mf][0], base + OFF_AH);
                ldm_x4(afr[mf][1], base + OFF_AL);
            }
            uint32_t bfr[4][2][4];   // [npair][hi/lo]
#pragma unroll
            for (int p = 0; p < 4; p++) {
                uint32_t base = buf + (uint32_t)(s * 16) * B_STRIDE + b_rowl
                              + b_col + p * 32;
                ldm_x4t(bfr[p][0], base + OFF_BH);
                ldm_x4t(bfr[p][1], base + OFF_BL);
            }
#pragma unroll
            for (int mf = 0; mf < 2; mf++)
#pragma unroll
                for (int p = 0; p < 4; p++)
#pragma unroll
                    for (int h = 0; h < 2; h++) {
                        float* c = acc[mf][p * 2 + h];
                        mma_bf16(c, afr[mf][0], &bfr[p][0][h * 2]);   // Ah*Bh
                        mma_bf16(c, afr[mf][0], &bfr[p][1][h * 2]);   // Ah*Bl
                        mma_bf16(c, afr[mf][1], &bfr[p][0][h * 2]);   // Al*Bh
                    }
        }

        if (ch < 3) {
            sts_regs((ch + 1) & 1);
            __syncthreads();
        }
    }

    // ---- epilogue: +bias, store fp32 ---------------------------------------
#pragma unroll
    for (int mf = 0; mf < 2; mf++) {
        int mrow0 = m0g + warpM * 32 + mf * 16 + (lane >> 2);
        float b0 = bias[mrow0];
        float b1 = bias[mrow0 + 8];
        int ncol = n0 + warpN * 64 + (lane & 3) * 2;
#pragma unroll
        for (int nf = 0; nf < 8; nf++) {
            float* c = acc[mf][nf];
            float2 v0 = make_float2(c[0] + b0, c[1] + b0);
            float2 v1 = make_float2(c[2] + b1, c[3] + b1);
            *(float2*)&outp[(size_t)mrow0 * SPAT + ncol + nf * 8]       = v0;
            *(float2*)&outp[(size_t)(mrow0 + 8) * SPAT + ncol + nf * 8] = v1;
        }
    }
}

// ---------------- fused branch: softmax-attn * v -> SE -> out_s, + sup prior
__global__ __launch_bounds__(256)
void branch_kernel(int ch_off,
                   const float* __restrict__ w1,   const float* __restrict__ b1,
                   const float* __restrict__ w2,   const float* __restrict__ b2,
                   const float* __restrict__ wsup, const float* __restrict__ bsup, int nsup,
                   float* __restrict__ out_s, float* __restrict__ sup_out)
{
    __shared__ float w1s[16 * 128];
    __shared__ float w2s[256 * 16];
    __shared__ float wss[6 * 128];
    __shared__ float b1s[16];
    __shared__ float b2s[256];
    __shared__ float bss[6];

    int tid = threadIdx.x;
    for (int i = tid; i < 2048; i += 256) w1s[i] = w1[i];
    for (int i = tid; i < 4096; i += 256) w2s[i] = w2[i];
    for (int i = tid; i < nsup * 128; i += 256) wss[i] = wsup[i];
    if (tid < 16)   b1s[tid] = b1[tid];
    if (tid < nsup) bss[tid] = bsup[tid];
    b2s[tid] = b2[tid];
    __syncthreads();

    int vg = blockIdx.x * 256 + tid;   // global voxel (b,s), < 65536
    int b  = vg >> 15;
    int s  = vg & (SPAT - 1);
    size_t base = (size_t)b * CCH * SPAT + (size_t)ch_off * SPAT + s;

    float tacc[16];
#pragma unroll
    for (int j = 0; j < 16; j++) tacc[j] = 0.f;
    float supacc[6] = {0.f, 0.f, 0.f, 0.f, 0.f, 0.f};

#pragma unroll 1
    for (int h = 0; h < 8; h++) {
        float qv[16], ev[16], vv[16];
#pragma unroll
        for (int i = 0; i < 16; i++) {
            size_t a = base + (size_t)(h * 16 + i) * SPAT;
            qv[i] = g_q[a];
            float kv = g_k[a];
            vv[i] = g_v[a];
            ev[i] = qv[i] * kv * 0.25f;   // SCALE = HD^-0.5 = 0.25
        }
        float m = ev[0];
#pragma unroll
        for (int i = 1; i < 16; i++) m = fmaxf(m, ev[i]);
        float ssum = 0.f;
#pragma unroll
        for (int i = 0; i < 16; i++) { ev[i] = __expf(ev[i] - m); ssum += ev[i]; }
        float inv = 1.f / ssum;
#pragma unroll
        for (int i = 0; i < 16; i++) {
            float o = ev[i] * inv * vv[i];
            int c = h * 16 + i;
#pragma unroll
            for (int j = 0; j < 16; j++) tacc[j] += w1s[j * 128 + c] * o;
            for (int j = 0; j < nsup; j++) supacc[j] += wss[j * 128 + c] * qv[i];
        }
    }
#pragma unroll
    for (int j = 0; j < 16; j++) tacc[j] = fmaxf(tacc[j] + b1s[j], 0.f);

    size_t obase = (size_t)b * CCH * SPAT + s;
#pragma unroll 4
    for (int o = 0; o < 256; o++) {
        float a = b2s[o];
#pragma unroll
        for (int j = 0; j < 16; j++) a += w2s[o * 16 + j] * tacc[j];
        out_s[obase + (size_t)o * SPAT] = 1.f / (1.f + __expf(-a));
    }
    size_t sbase = (size_t)b * nsup * SPAT + s;
    for (int j = 0; j < nsup; j++)
        sup_out[sbase + (size_t)j * SPAT] = supacc[j] + bss[j];
}

// ---------------- deterministic max/mean/min pooling ------------------------
__global__ __launch_bounds__(256)
void pool_kernel(const float* __restrict__ outbase)
{
    __shared__ float smx[256], smn[256], ssm[256];
    int blk = blockIdx.x;        // 0..1023 : region*512 + b*256 + c
    int r   = blk >> 9;
    int bc  = blk & 511;
    const float* p = outbase + (size_t)r * REG_SZ + (size_t)bc * SPAT;
    int tid = threadIdx.x;
    float mx = -1e30f, mn = 1e30f, sm = 0.f;
    for (int i = tid; i < SPAT; i += 256) {
        float v = p[i];
        mx = fmaxf(mx, v); mn = fminf(mn, v); sm += v;
    }
    smx[tid] = mx; smn[tid] = mn; ssm[tid] = sm;
    __syncthreads();
    for (int st = 128; st > 0; st >>= 1) {
        if (tid < st) {
            smx[tid] = fmaxf(smx[tid], smx[tid + st]);
            smn[tid] = fminf(smn[tid], smn[tid + st]);
            ssm[tid] += ssm[tid + st];
        }
        __syncthreads();
    }
    if (tid == 0) {
        g_pool[blk * 3 + 0] = smx[0];
        g_pool[blk * 3 + 1] = ssm[0] * (1.f / 32768.f);
        g_pool[blk * 3 + 2] = smn[0];
    }
}

// ---------------- gate: Conv1d(3->1) + FC squeeze-excite --------------------
__global__ __launch_bounds__(256)
void gate_kernel(const float* __restrict__ sq1w, const float* __restrict__ sq1b,
                 const float* __restrict__ sq2w, const float* __restrict__ sq2b,
                 const float* __restrict__ f1w1, const float* __restrict__ f1b1,
                 const float* __restrict__ f1w2, const float* __restrict__ f1b2,
                 const float* __restrict__ f2w1, const float* __restrict__ f2b1,
                 const float* __restrict__ f2w2, const float* __restrict__ f2b2)
{
    int r = blockIdx.x >> 1, b = blockIdx.x & 1;
    const float* sqw = r ? sq2w : sq1w;
    const float* sqb = r ? sq2b : sq1b;
    const float* fw1 = r ? f2w1 : f1w1;
    const float* fb1 = r ? f2b1 : f1b1;
    const float* fw2 = r ? f2w2 : f1w2;
    const float* fb2 = r ? f2b2 : f1b2;

    __shared__ float sqs[256], hs[16];
    int c = threadIdx.x;
    const float* pr = &g_pool[(r * 512 + b * 256 + c) * 3];
    sqs[c] = pr[0] * sqw[0] + pr[1] * sqw[1] + pr[2] * sqw[2] + sqb[0];
    __syncthreads();
    if (c < 16) {
        float a = fb1[c];
        for (int j = 0; j < 256; j++) a += fw1[c * 256 + j] * sqs[j];
        hs[c] = fmaxf(a, 0.f);
    }
    __syncthreads();
    float a = fb2[c];
#pragma unroll
    for (int j = 0; j < 16; j++) a += fw2[c * 16 + j] * hs[j];
    g_gate[r * 512 + b * 256 + c] = 1.f / (1.f + __expf(-a));
}

// ---------------- apply gate in place on out1|out2 --------------------------
__global__ __launch_bounds__(256)
void scale_kernel(float* __restrict__ out)
{
    size_t i = (size_t)blockIdx.x * 256 + threadIdx.x;  // float4 index, < 8388608
    int r  = (int)(i >> 22);            // 4194304 float4 per region
    int bc = (int)((i >> 13) & 511);    // 8192 float4 per (b,c) row
    float g = g_gate[r * 512 + bc];
    float4* p = ((float4*)out) + i;
    float4 v = *p;
    v.x *= g; v.y *= g; v.z *= g; v.w *= g;
    *p = v;
}

// ---------------- launch ----------------------------------------------------
extern "C" void kernel_launch(void* const* d_in, const int* in_sizes, int n_in,
                              void* d_out, int out_size)
{
    const float* x      = (const float*)d_in[0];
    const float* Wq     = (const float*)d_in[1];
    const float* bq     = (const float*)d_in[2];
    const float* Wk     = (const float*)d_in[3];
    const float* bk     = (const float*)d_in[4];
    const float* Wv     = (const float*)d_in[5];
    const float* bv     = (const float*)d_in[6];
    const float* Wq1p   = (const float*)d_in[7];
    const float* bq1p   = (const float*)d_in[8];
    const float* Wq2p   = (const float*)d_in[9];
    const float* bq2p   = (const float*)d_in[10];
    const float* sq1_w  = (const float*)d_in[11];
    const float* sq1_b  = (const float*)d_in[12];
    const float* sq2_w  = (const float*)d_in[13];
    const float* sq2_b  = (const float*)d_in[14];
    const float* se1_w1 = (const float*)d_in[15];
    const float* se1_b1 = (const float*)d_in[16];
    const float* se1_w2 = (const float*)d_in[17];
    const float* se1_b2 = (const float*)d_in[18];
    const float* se2_w1 = (const float*)d_in[19];
    const float* se2_b1 = (const float*)d_in[20];
    const float* se2_w2 = (const float*)d_in[21];
    const float* se2_b2 = (const float*)d_in[22];
    const float* sec1_w1 = (const float*)d_in[23];
    const float* sec1_b1 = (const float*)d_in[24];
    const float* sec1_w2 = (const float*)d_in[25];
    const float* sec1_b2 = (const float*)d_in[26];
    const float* sec2_w1 = (const float*)d_in[27];
    const float* sec2_b1 = (const float*)d_in[28];
    const float* sec2_w2 = (const float*)d_in[29];
    const float* sec2_b2 = (const float*)d_in[30];

    float* out  = (float*)d_out;
    float* out1 = out;
    float* out2 = out + (size_t)REG_SZ;            // 16777216
    float* sup1 = out + (size_t)2 * REG_SZ;        // 33554432
    float* sup2 = sup1 + 2 * 6 * SPAT;             // 33947648

    cudaFuncSetAttribute(qkv_gemm_mma, cudaFuncAttributeMaxDynamicSharedMemorySize,
                         GEMM_SMEM);
    dim3 gg(256, 2, 6);   // ntiles, mtiles, mat*2+batch
    qkv_gemm_mma<<<gg, 256, GEMM_SMEM>>>(x, Wq, bq, Wk, bk, Wv, bv);

    branch_kernel<<<256, 256>>>(0,   se1_w1, se1_b1, se1_w2, se1_b2,
                                Wq1p, bq1p, 6, out1, sup1);
    branch_kernel<<<256, 256>>>(128, se2_w1, se2_b1, se2_w2, se2_b2,
                                Wq2p, bq2p, 1, out2, sup2);

    pool_kernel<<<1024, 256>>>(out);

    gate_kernel<<<4, 256>>>(sq1_w, sq1_b, sq2_w, sq2_b,
                            sec1_w1, sec1_b1, sec1_w2, sec1_b2,
                            sec2_w1, sec2_b1, sec2_w2, sec2_b2);

    scale_kernel<<<32768, 256>>>(out);
}

// round 4
// speedup vs baseline: 1.6442x; 1.0541x over previous
#include <cuda_runtime.h>
#include <cuda_bf16.h>
#include <math.h>
#include <stdint.h>

#define SPAT 32768           // D*H*W
#define CCH  256             // channels
#define REG_SZ (2*256*32768) // one region (b, 256, 32768)

// ---------------- scratch (device globals; no allocations allowed) ----------
__device__ float g_q[REG_SZ];
__device__ float g_k[REG_SZ];
__device__ float g_v[REG_SZ];
__device__ __nv_bfloat16 g_xh[REG_SZ];      // x hi bf16
__device__ __nv_bfloat16 g_xl[REG_SZ];      // x lo bf16
__device__ __nv_bfloat16 g_wh[3 * 256 * 256];
__device__ __nv_bfloat16 g_wl[3 * 256 * 256];
__device__ float g_pool[2 * 512 * 3];   // [region][b*256+c][max,avg,min]
__device__ float g_gate[2 * 512];       // [region][b*256+c]

// ======================= helpers ============================================
__device__ __forceinline__ uint32_t smem_u32(const void* p) {
    uint32_t a;
    asm("{ .reg .u64 t; cvta.to.shared.u64 t, %1; cvt.u32.u64 %0, t; }"
        : "=r"(a) : "l"(p));
    return a;
}
__device__ __forceinline__ void cp16(uint32_t dst, const void* src) {
    asm volatile("cp.async.cg.shared.global [%0], [%1], 16;"
                 :: "r"(dst), "l"(src) : "memory");
}
#define CP_COMMIT() asm volatile("cp.async.commit_group;" ::: "memory")
#define CP_WAIT(n)  asm volatile("cp.async.wait_group %0;" :: "n"(n) : "memory")

__device__ __forceinline__ void ldm_x4(uint32_t* r, uint32_t a) {
    asm volatile("ldmatrix.sync.aligned.m8n8.x4.shared.b16 {%0,%1,%2,%3}, [%4];"
        : "=r"(r[0]), "=r"(r[1]), "=r"(r[2]), "=r"(r[3]) : "r"(a));
}
__device__ __forceinline__ void ldm_x4t(uint32_t* r, uint32_t a) {
    asm volatile("ldmatrix.sync.aligned.m8n8.x4.trans.shared.b16 {%0,%1,%2,%3}, [%4];"
        : "=r"(r[0]), "=r"(r[1]), "=r"(r[2]), "=r"(r[3]) : "r"(a));
}
__device__ __forceinline__ void mma_bf16(float* c, const uint32_t* a, const uint32_t* b) {
    asm volatile(
        "mma.sync.aligned.m16n8k16.row.col.f32.bf16.bf16.f32 "
        "{%0,%1,%2,%3}, {%4,%5,%6,%7}, {%8,%9}, {%0,%1,%2,%3};"
        : "+f"(c[0]), "+f"(c[1]), "+f"(c[2]), "+f"(c[3])
        : "r"(a[0]), "r"(a[1]), "r"(a[2]), "r"(a[3]), "r"(b[0]), "r"(b[1]));
}

// ---------------- pre-convert: fp32 -> bf16 hi/lo ---------------------------
__device__ __forceinline__ void split4_pack(float4 v, uint2& h, uint2& l) {
    __nv_bfloat16 hx = __float2bfloat16_rn(v.x), hy = __float2bfloat16_rn(v.y);
    __nv_bfloat16 hz = __float2bfloat16_rn(v.z), hw = __float2bfloat16_rn(v.w);
    __nv_bfloat16 lx = __float2bfloat16_rn(v.x - __bfloat162float(hx));
    __nv_bfloat16 ly = __float2bfloat16_rn(v.y - __bfloat162float(hy));
    __nv_bfloat16 lz = __float2bfloat16_rn(v.z - __bfloat162float(hz));
    __nv_bfloat16 lw = __float2bfloat16_rn(v.w - __bfloat162float(hw));
    h.x = (uint32_t)__bfloat16_as_ushort(hx) | ((uint32_t)__bfloat16_as_ushort(hy) << 16);
    h.y = (uint32_t)__bfloat16_as_ushort(hz) | ((uint32_t)__bfloat16_as_ushort(hw) << 16);
    l.x = (uint32_t)__bfloat16_as_ushort(lx) | ((uint32_t)__bfloat16_as_ushort(ly) << 16);
    l.y = (uint32_t)__bfloat16_as_ushort(lz) | ((uint32_t)__bfloat16_as_ushort(lw) << 16);
}

__global__ __launch_bounds__(256)
void convert_x(const float* __restrict__ x)
{
    size_t i = (size_t)blockIdx.x * 256 + threadIdx.x;   // float4 idx, < 4194304
    float4 v = ((const float4*)x)[i];
    uint2 h, l; split4_pack(v, h, l);
    *(uint2*)&g_xh[i * 4] = h;
    *(uint2*)&g_xl[i * 4] = l;
}

__global__ __launch_bounds__(256)
void convert_w(const float* __restrict__ Wq, const float* __restrict__ Wk,
               const float* __restrict__ Wv)
{
    int mat = blockIdx.y;
    const float* W = (mat == 0) ? Wq : ((mat == 1) ? Wk : Wv);
    size_t i = (size_t)blockIdx.x * 256 + threadIdx.x;   // float4 idx, < 16384
    float4 v = ((const float4*)W)[i];
    uint2 h, l; split4_pack(v, h, l);
    *(uint2*)&g_wh[(size_t)mat * 65536 + i * 4] = h;
    *(uint2*)&g_wl[(size_t)mat * 65536 + i * 4] = l;
}

// ---------------- SMEM layout (per buffer, 71680 B; double buffered) --------
#define A_STRIDE 144
#define B_STRIDE 272
#define OFF_AH 0
#define OFF_AL 18432
#define OFF_BH 36864
#define OFF_BL 54272
#define BUF_SZ 71680
#define GEMM_SMEM (2 * BUF_SZ)

// ================== mma.sync QKV GEMM (cp.async bf16) =======================
// grid: (256 ntiles, 2 mtiles, 6 = mat*2+batch); 256 threads (8 warps: 4M x 2N)
__global__ __launch_bounds__(256, 1)
void qkv_gemm_mma(const float* __restrict__ bq, const float* __restrict__ bk,
                  const float* __restrict__ bv)
{
    extern __shared__ char sm[];
    const uint32_t smb = smem_u32(sm);

    const int tid   = threadIdx.x;
    const int warp  = tid >> 5, lane = tid & 31;
    const int warpM = warp >> 1, warpN = warp & 1;
    const int n0    = blockIdx.x * 128;
    const int m0g   = blockIdx.y * 128;
    const int mat   = blockIdx.z >> 1, bb = blockIdx.z & 1;

    const float* bias = (mat == 0) ? bq : ((mat == 1) ? bk : bv);
    float* outp = ((mat == 0) ? g_q : ((mat == 1) ? g_k : g_v))
                  + (size_t)bb * CCH * SPAT;
    const __nv_bfloat16* Wh = g_wh + (size_t)mat * 65536;
    const __nv_bfloat16* Wl = g_wl + (size_t)mat * 65536;
    const __nv_bfloat16* Xh = g_xh + (size_t)bb * CCH * SPAT + n0;
    const __nv_bfloat16* Xl = g_xl + (size_t)bb * CCH * SPAT + n0;

    // ---- async tile fetch of k-chunk `ch` into buffer `buf` ---------------
    auto issue = [&](int ch, int buf) {
        const uint32_t base = smb + buf * BUF_SZ;
        const int kc0 = ch << 6;
#pragma unroll
        for (int t = 0; t < 4; t++) {
            int idx = tid + t * 256;           // 0..1023
            int row = idx >> 3, piece = idx & 7;
            uint32_t doff = (uint32_t)row * A_STRIDE + piece * 16;
            size_t soff = (size_t)(m0g + row) * 256 + kc0 + piece * 8;
            cp16(base + OFF_AH + doff, Wh + soff);
            cp16(base + OFF_AL + doff, Wl + soff);
        }
#pragma unroll
        for (int t = 0; t < 4; t++) {
            int idx = tid + t * 256;
            int row = idx >> 4, piece = idx & 15;
            uint32_t doff = (uint32_t)row * B_STRIDE + piece * 16;
            size_t soff = (size_t)(kc0 + row) * SPAT + piece * 8;
            cp16(base + OFF_BH + doff, Xh + soff);
            cp16(base + OFF_BL + doff, Xl + soff);
        }
        CP_COMMIT();
    };

    float acc[2][8][4];
#pragma unroll
    for (int i = 0; i < 2; i++)
#pragma unroll
        for (int j = 0; j < 8; j++)
#pragma unroll
            for (int c = 0; c < 4; c++) acc[i][j][c] = 0.f;

    issue(0, 0);
    issue(1, 1);

#pragma unroll 1
    for (int ch = 0; ch < 4; ch++) {
        if (ch < 3) { CP_WAIT(1); } else { CP_WAIT(0); }
        __syncthreads();

        const uint32_t buf = smb + (ch & 1) * BUF_SZ;
        const uint32_t a_row  = (warpM * 32 + (lane & 15)) * A_STRIDE + (lane >> 4) * 16;
        const uint32_t b_col  = (warpN * 64) * 2 + (lane >> 4) * 16;
        const uint32_t b_rowl = (lane & 15) * B_STRIDE;

#pragma unroll
        for (int s = 0; s < 4; s++) {
            uint32_t afr[2][2][4];   // [mf][hi/lo]
#pragma unroll
            for (int mf = 0; mf < 2; mf++) {
                uint32_t base = buf + a_row + mf * (16 * A_STRIDE) + s * 32;
                ldm_x4(afr[mf][0], base + OFF_AH);
                ldm_x4(afr[mf][1], base + OFF_AL);
            }
            uint32_t bfr[4][2][4];   // [npair][hi/lo]
#pragma unroll
            for (int p = 0; p < 4; p++) {
                uint32_t base = buf + (uint32_t)(s * 16) * B_STRIDE + b_rowl
                              + b_col + p * 32;
                ldm_x4t(bfr[p][0], base + OFF_BH);
                ldm_x4t(bfr[p][1], base + OFF_BL);
            }
#pragma unroll
            for (int mf = 0; mf < 2; mf++)
#pragma unroll
                for (int p = 0; p < 4; p++)
#pragma unroll
                    for (int h = 0; h < 2; h++) {
                        float* c = acc[mf][p * 2 + h];
                        mma_bf16(c, afr[mf][0], &bfr[p][0][h * 2]);   // Ah*Bh
                        mma_bf16(c, afr[mf][0], &bfr[p][1][h * 2]);   // Ah*Bl
                        mma_bf16(c, afr[mf][1], &bfr[p][0][h * 2]);   // Al*Bh
                    }
        }
        __syncthreads();
        if (ch < 2) issue(ch + 2, ch & 1);
    }

    // ---- epilogue: +bias, store fp32 ---------------------------------------
#pragma unroll
    for (int mf = 0; mf < 2; mf++) {
        int mrow0 = m0g + warpM * 32 + mf * 16 + (lane >> 2);
        float b0 = bias[mrow0];
        float b1 = bias[mrow0 + 8];
        int ncol = n0 + warpN * 64 + (lane & 3) * 2;
#pragma unroll
        for (int nf = 0; nf < 8; nf++) {
            float* c = acc[mf][nf];
            float2 v0 = make_float2(c[0] + b0, c[1] + b0);
            float2 v1 = make_float2(c[2] + b1, c[3] + b1);
            *(float2*)&outp[(size_t)mrow0 * SPAT + ncol + nf * 8]       = v0;
            *(float2*)&outp[(size_t)(mrow0 + 8) * SPAT + ncol + nf * 8] = v1;
        }
    }
}

// ---------------- fused branch: softmax-attn * v -> SE -> out_s, + sup prior
__global__ __launch_bounds__(256)
void branch_kernel(int ch_off,
                   const float* __restrict__ w1,   const float* __restrict__ b1,
                   const float* __restrict__ w2,   const float* __restrict__ b2,
                   const float* __restrict__ wsup, const float* __restrict__ bsup, int nsup,
                   float* __restrict__ out_s, float* __restrict__ sup_out)
{
    __shared__ float w1s[16 * 128];
    __shared__ float w2s[256 * 16];
    __shared__ float wss[6 * 128];
    __shared__ float b1s[16];
    __shared__ float b2s[256];
    __shared__ float bss[6];

    int tid = threadIdx.x;
    for (int i = tid; i < 2048; i += 256) w1s[i] = w1[i];
    for (int i = tid; i < 4096; i += 256) w2s[i] = w2[i];
    for (int i = tid; i < nsup * 128; i += 256) wss[i] = wsup[i];
    if (tid < 16)   b1s[tid] = b1[tid];
    if (tid < nsup) bss[tid] = bsup[tid];
    b2s[tid] = b2[tid];
    __syncthreads();

    int vg = blockIdx.x * 256 + tid;   // global voxel (b,s), < 65536
    int b  = vg >> 15;
    int s  = vg & (SPAT - 1);
    size_t base = (size_t)b * CCH * SPAT + (size_t)ch_off * SPAT + s;

    float tacc[16];
#pragma unroll
    for (int j = 0; j < 16; j++) tacc[j] = 0.f;
    float supacc[6] = {0.f, 0.f, 0.f, 0.f, 0.f, 0.f};

#pragma unroll 1
    for (int h = 0; h < 8; h++) {
        float qv[16], ev[16], vv[16];
#pragma unroll
        for (int i = 0; i < 16; i++) {
            size_t a = base + (size_t)(h * 16 + i) * SPAT;
            qv[i] = g_q[a];
            float kv = g_k[a];
            vv[i] = g_v[a];
            ev[i] = qv[i] * kv * 0.25f;   // SCALE = HD^-0.5 = 0.25
        }
        float m = ev[0];
#pragma unroll
        for (int i = 1; i < 16; i++) m = fmaxf(m, ev[i]);
        float ssum = 0.f;
#pragma unroll
        for (int i = 0; i < 16; i++) { ev[i] = __expf(ev[i] - m); ssum += ev[i]; }
        float inv = 1.f / ssum;
#pragma unroll
        for (int i = 0; i < 16; i++) {
            float o = ev[i] * inv * vv[i];
            int c = h * 16 + i;
#pragma unroll
            for (int j = 0; j < 16; j++) tacc[j] += w1s[j * 128 + c] * o;
            for (int j = 0; j < nsup; j++) supacc[j] += wss[j * 128 + c] * qv[i];
        }
    }
#pragma unroll
    for (int j = 0; j < 16; j++) tacc[j] = fmaxf(tacc[j] + b1s[j], 0.f);

    size_t obase = (size_t)b * CCH * SPAT + s;
#pragma unroll 4
    for (int o = 0; o < 256; o++) {
        float a = b2s[o];
#pragma unroll
        for (int j = 0; j < 16; j++) a += w2s[o * 16 + j] * tacc[j];
        out_s[obase + (size_t)o * SPAT] = 1.f / (1.f + __expf(-a));
    }
    size_t sbase = (size_t)b * nsup * SPAT + s;
    for (int j = 0; j < nsup; j++)
        sup_out[sbase + (size_t)j * SPAT] = supacc[j] + bss[j];
}

// ---------------- deterministic max/mean/min pooling ------------------------
__global__ __launch_bounds__(256)
void pool_kernel(const float* __restrict__ outbase)
{
    __shared__ float smx[256], smn[256], ssm[256];
    int blk = blockIdx.x;        // 0..1023 : region*512 + b*256 + c
    int r   = blk >> 9;
    int bc  = blk & 511;
    const float* p = outbase + (size_t)r * REG_SZ + (size_t)bc * SPAT;
    int tid = threadIdx.x;
    float mx = -1e30f, mn = 1e30f, sm = 0.f;
    for (int i = tid; i < SPAT; i += 256) {
        float v = p[i];
        mx = fmaxf(mx, v); mn = fminf(mn, v); sm += v;
    }
    smx[tid] = mx; smn[tid] = mn; ssm[tid] = sm;
    __syncthreads();
    for (int st = 128; st > 0; st >>= 1) {
        if (tid < st) {
            smx[tid] = fmaxf(smx[tid], smx[tid + st]);
            smn[tid] = fminf(smn[tid], smn[tid + st]);
            ssm[tid] += ssm[tid + st];
        }
        __syncthreads();
    }
    if (tid == 0) {
        g_pool[blk * 3 + 0] = smx[0];
        g_pool[blk * 3 + 1] = ssm[0] * (1.f / 32768.f);
        g_pool[blk * 3 + 2] = smn[0];
    }
}

// ---------------- gate: Conv1d(3->1) + FC squeeze-excite --------------------
__global__ __launch_bounds__(256)
void gate_kernel(const float* __restrict__ sq1w, const float* __restrict__ sq1b,
                 const float* __restrict__ sq2w, const float* __restrict__ sq2b,
                 const float* __restrict__ f1w1, const float* __restrict__ f1b1,
                 const float* __restrict__ f1w2, const float* __restrict__ f1b2,
                 const float* __restrict__ f2w1, const float* __restrict__ f2b1,
                 const float* __restrict__ f2w2, const float* __restrict__ f2b2)
{
    int r = blockIdx.x >> 1, b = blockIdx.x & 1;
    const float* sqw = r ? sq2w : sq1w;
    const float* sqb = r ? sq2b : sq1b;
    const float* fw1 = r ? f2w1 : f1w1;
    const float* fb1 = r ? f2b1 : f1b1;
    const float* fw2 = r ? f2w2 : f1w2;
    const float* fb2 = r ? f2b2 : f1b2;

    __shared__ float sqs[256], hs[16];
    int c = threadIdx.x;
    const float* pr = &g_pool[(r * 512 + b * 256 + c) * 3];
    sqs[c] = pr[0] * sqw[0] + pr[1] * sqw[1] + pr[2] * sqw[2] + sqb[0];
    __syncthreads();
    if (c < 16) {
        float a = fb1[c];
        for (int j = 0; j < 256; j++) a += fw1[c * 256 + j] * sqs[j];
        hs[c] = fmaxf(a, 0.f);
    }
    __syncthreads();
    float a = fb2[c];
#pragma unroll
    for (int j = 0; j < 16; j++) a += fw2[c * 16 + j] * hs[j];
    g_gate[r * 512 + b * 256 + c] = 1.f / (1.f + __expf(-a));
}

// ---------------- apply gate in place on out1|out2 --------------------------
__global__ __launch_bounds__(256)
void scale_kernel(float* __restrict__ out)
{
    size_t i = (size_t)blockIdx.x * 256 + threadIdx.x;  // float4 index, < 8388608
    int r  = (int)(i >> 22);            // 4194304 float4 per region
    int bc = (int)((i >> 13) & 511);    // 8192 float4 per (b,c) row
    float g = g_gate[r * 512 + bc];
    float4* p = ((float4*)out) + i;
    float4 v = *p;
    v.x *= g; v.y *= g; v.z *= g; v.w *= g;
    *p = v;
}

// ---------------- launch ----------------------------------------------------
extern "C" void kernel_launch(void* const* d_in, const int* in_sizes, int n_in,
                              void* d_out, int out_size)
{
    const float* x      = (const float*)d_in[0];
    const float* Wq     = (const float*)d_in[1];
    const float* bq     = (const float*)d_in[2];
    const float* Wk     = (const float*)d_in[3];
    const float* bk     = (const float*)d_in[4];
    const float* Wv     = (const float*)d_in[5];
    const float* bv     = (const float*)d_in[6];
    const float* Wq1p   = (const float*)d_in[7];
    const float* bq1p   = (const float*)d_in[8];
    const float* Wq2p   = (const float*)d_in[9];
    const float* bq2p   = (const float*)d_in[10];
    const float* sq1_w  = (const float*)d_in[11];
    const float* sq1_b  = (const float*)d_in[12];
    const float* sq2_w  = (const float*)d_in[13];
    const float* sq2_b  = (const float*)d_in[14];
    const float* se1_w1 = (const float*)d_in[15];
    const float* se1_b1 = (const float*)d_in[16];
    const float* se1_w2 = (const float*)d_in[17];
    const float* se1_b2 = (const float*)d_in[18];
    const float* se2_w1 = (const float*)d_in[19];
    const float* se2_b1 = (const float*)d_in[20];
    const float* se2_w2 = (const float*)d_in[21];
    const float* se2_b2 = (const float*)d_in[22];
    const float* sec1_w1 = (const float*)d_in[23];
    const float* sec1_b1 = (const float*)d_in[24];
    const float* sec1_w2 = (const float*)d_in[25];
    const float* sec1_b2 = (const float*)d_in[26];
    const float* sec2_w1 = (const float*)d_in[27];
    const float* sec2_b1 = (const float*)d_in[28];
    const float* sec2_w2 = (const float*)d_in[29];
    const float* sec2_b2 = (const float*)d_in[30];

    float* out  = (float*)d_out;
    float* out1 = out;
    float* out2 = out + (size_t)REG_SZ;            // 16777216
    float* sup1 = out + (size_t)2 * REG_SZ;        // 33554432
    float* sup2 = sup1 + 2 * 6 * SPAT;             // 33947648

    convert_x<<<16384, 256>>>(x);
    dim3 gw(64, 3);
    convert_w<<<gw, 256>>>(Wq, Wk, Wv);

    cudaFuncSetAttribute(qkv_gemm_mma, cudaFuncAttributeMaxDynamicSharedMemorySize,
                         GEMM_SMEM);
    dim3 gg(256, 2, 6);   // ntiles, mtiles, mat*2+batch
    qkv_gemm_mma<<<gg, 256, GEMM_SMEM>>>(bq, bk, bv);

    branch_kernel<<<256, 256>>>(0,   se1_w1, se1_b1, se1_w2, se1_b2,
                                Wq1p, bq1p, 6, out1, sup1);
    branch_kernel<<<256, 256>>>(128, se2_w1, se2_b1, se2_w2, se2_b2,
                                Wq2p, bq2p, 1, out2, sup2);

    pool_kernel<<<1024, 256>>>(out);

    gate_kernel<<<4, 256>>>(sq1_w, sq1_b, sq2_w, sq2_b,
                            sec1_w1, sec1_b1, sec1_w2, sec1_b2,
                            sec2_w1, sec2_b1, sec2_w2, sec2_b2);

    scale_kernel<<<32768, 256>>>(out);
}

// round 5
// speedup vs baseline: 1.8264x; 1.1108x over previous
#include <cuda_runtime.h>
#include <cuda_bf16.h>
#include <math.h>
#include <stdint.h>

#define SPAT 32768           // D*H*W
#define CCH  256             // channels
#define REG_SZ (2*256*32768) // one region (b, 256, 32768)

// ---------------- scratch (device globals; no allocations allowed) ----------
__device__ float g_q[REG_SZ];
__device__ float g_k[REG_SZ];
__device__ float g_v[REG_SZ];
__device__ float g_t[2 * 16 * 65536];       // [branch][j][b*32768+s]
__device__ __nv_bfloat16 g_xh[REG_SZ];      // x hi bf16
__device__ __nv_bfloat16 g_xl[REG_SZ];      // x lo bf16
__device__ __nv_bfloat16 g_wh[3 * 256 * 256];
__device__ __nv_bfloat16 g_wl[3 * 256 * 256];
__device__ float g_pool[2 * 512 * 3];   // [region][b*256+c][max,avg,min]
__device__ float g_gate[2 * 512];       // [region][b*256+c]

// ======================= helpers ============================================
__device__ __forceinline__ uint32_t smem_u32(const void* p) {
    uint32_t a;
    asm("{ .reg .u64 t; cvta.to.shared.u64 t, %1; cvt.u32.u64 %0, t; }"
        : "=r"(a) : "l"(p));
    return a;
}
__device__ __forceinline__ void cp16(uint32_t dst, const void* src) {
    asm volatile("cp.async.cg.shared.global [%0], [%1], 16;"
                 :: "r"(dst), "l"(src) : "memory");
}
#define CP_COMMIT() asm volatile("cp.async.commit_group;" ::: "memory")
#define CP_WAIT(n)  asm volatile("cp.async.wait_group %0;" :: "n"(n) : "memory")

__device__ __forceinline__ void ldm_x4(uint32_t* r, uint32_t a) {
    asm volatile("ldmatrix.sync.aligned.m8n8.x4.shared.b16 {%0,%1,%2,%3}, [%4];"
        : "=r"(r[0]), "=r"(r[1]), "=r"(r[2]), "=r"(r[3]) : "r"(a));
}
__device__ __forceinline__ void ldm_x4t(uint32_t* r, uint32_t a) {
    asm volatile("ldmatrix.sync.aligned.m8n8.x4.trans.shared.b16 {%0,%1,%2,%3}, [%4];"
        : "=r"(r[0]), "=r"(r[1]), "=r"(r[2]), "=r"(r[3]) : "r"(a));
}
__device__ __forceinline__ void mma_bf16(float* c, const uint32_t* a, const uint32_t* b) {
    asm volatile(
        "mma.sync.aligned.m16n8k16.row.col.f32.bf16.bf16.f32 "
        "{%0,%1,%2,%3}, {%4,%5,%6,%7}, {%8,%9}, {%0,%1,%2,%3};"
        : "+f"(c[0]), "+f"(c[1]), "+f"(c[2]), "+f"(c[3])
        : "r"(a[0]), "r"(a[1]), "r"(a[2]), "r"(a[3]), "r"(b[0]), "r"(b[1]));
}

// ---------------- pre-convert: fp32 -> bf16 hi/lo ---------------------------
__device__ __forceinline__ void split4_pack(float4 v, uint2& h, uint2& l) {
    __nv_bfloat16 hx = __float2bfloat16_rn(v.x), hy = __float2bfloat16_rn(v.y);
    __nv_bfloat16 hz = __float2bfloat16_rn(v.z), hw = __float2bfloat16_rn(v.w);
    __nv_bfloat16 lx = __float2bfloat16_rn(v.x - __bfloat162float(hx));
    __nv_bfloat16 ly = __float2bfloat16_rn(v.y - __bfloat162float(hy));
    __nv_bfloat16 lz = __float2bfloat16_rn(v.z - __bfloat162float(hz));
    __nv_bfloat16 lw = __float2bfloat16_rn(v.w - __bfloat162float(hw));
    h.x = (uint32_t)__bfloat16_as_ushort(hx) | ((uint32_t)__bfloat16_as_ushort(hy) << 16);
    h.y = (uint32_t)__bfloat16_as_ushort(hz) | ((uint32_t)__bfloat16_as_ushort(hw) << 16);
    l.x = (uint32_t)__bfloat16_as_ushort(lx) | ((uint32_t)__bfloat16_as_ushort(ly) << 16);
    l.y = (uint32_t)__bfloat16_as_ushort(lz) | ((uint32_t)__bfloat16_as_ushort(lw) << 16);
}

__global__ __launch_bounds__(256)
void convert_x(const float* __restrict__ x)
{
    size_t i = (size_t)blockIdx.x * 256 + threadIdx.x;   // float4 idx, < 4194304
    float4 v = ((const float4*)x)[i];
    uint2 h, l; split4_pack(v, h, l);
    *(uint2*)&g_xh[i * 4] = h;
    *(uint2*)&g_xl[i * 4] = l;
}

__global__ __launch_bounds__(256)
void convert_w(const float* __restrict__ Wq, const float* __restrict__ Wk,
               const float* __restrict__ Wv)
{
    int mat = blockIdx.y;
    const float* W = (mat == 0) ? Wq : ((mat == 1) ? Wk : Wv);
    size_t i = (size_t)blockIdx.x * 256 + threadIdx.x;   // float4 idx, < 16384
    float4 v = ((const float4*)W)[i];
    uint2 h, l; split4_pack(v, h, l);
    *(uint2*)&g_wh[(size_t)mat * 65536 + i * 4] = h;
    *(uint2*)&g_wl[(size_t)mat * 65536 + i * 4] = l;
}

// ---------------- SMEM layout (per buffer, 71680 B; double buffered) --------
#define A_STRIDE 144
#define B_STRIDE 272
#define OFF_AH 0
#define OFF_AL 18432
#define OFF_BH 36864
#define OFF_BL 54272
#define BUF_SZ 71680
#define GEMM_SMEM (2 * BUF_SZ)

// ================== mma.sync QKV GEMM (cp.async bf16) =======================
__global__ __launch_bounds__(256, 1)
void qkv_gemm_mma(const float* __restrict__ bq, const float* __restrict__ bk,
                  const float* __restrict__ bv)
{
    extern __shared__ char sm[];
    const uint32_t smb = smem_u32(sm);

    const int tid   = threadIdx.x;
    const int warp  = tid >> 5, lane = tid & 31;
    const int warpM = warp >> 1, warpN = warp & 1;
    const int n0    = blockIdx.x * 128;
    const int m0g   = blockIdx.y * 128;
    const int mat   = blockIdx.z >> 1, bb = blockIdx.z & 1;

    const float* bias = (mat == 0) ? bq : ((mat == 1) ? bk : bv);
    float* outp = ((mat == 0) ? g_q : ((mat == 1) ? g_k : g_v))
                  + (size_t)bb * CCH * SPAT;
    const __nv_bfloat16* Wh = g_wh + (size_t)mat * 65536;
    const __nv_bfloat16* Wl = g_wl + (size_t)mat * 65536;
    const __nv_bfloat16* Xh = g_xh + (size_t)bb * CCH * SPAT + n0;
    const __nv_bfloat16* Xl = g_xl + (size_t)bb * CCH * SPAT + n0;

    auto issue = [&](int ch, int buf) {
        const uint32_t base = smb + buf * BUF_SZ;
        const int kc0 = ch << 6;
#pragma unroll
        for (int t = 0; t < 4; t++) {
            int idx = tid + t * 256;           // 0..1023
            int row = idx >> 3, piece = idx & 7;
            uint32_t doff = (uint32_t)row * A_STRIDE + piece * 16;
            size_t soff = (size_t)(m0g + row) * 256 + kc0 + piece * 8;
            cp16(base + OFF_AH + doff, Wh + soff);
            cp16(base + OFF_AL + doff, Wl + soff);
        }
#pragma unroll
        for (int t = 0; t < 4; t++) {
            int idx = tid + t * 256;
            int row = idx >> 4, piece = idx & 15;
            uint32_t doff = (uint32_t)row * B_STRIDE + piece * 16;
            size_t soff = (size_t)(kc0 + row) * SPAT + piece * 8;
            cp16(base + OFF_BH + doff, Xh + soff);
            cp16(base + OFF_BL + doff, Xl + soff);
        }
        CP_COMMIT();
    };

    float acc[2][8][4];
#pragma unroll
    for (int i = 0; i < 2; i++)
#pragma unroll
        for (int j = 0; j < 8; j++)
#pragma unroll
            for (int c = 0; c < 4; c++) acc[i][j][c] = 0.f;

    issue(0, 0);
    issue(1, 1);

#pragma unroll 1
    for (int ch = 0; ch < 4; ch++) {
        if (ch < 3) { CP_WAIT(1); } else { CP_WAIT(0); }
        __syncthreads();

        const uint32_t buf = smb + (ch & 1) * BUF_SZ;
        const uint32_t a_row  = (warpM * 32 + (lane & 15)) * A_STRIDE + (lane >> 4) * 16;
        const uint32_t b_col  = (warpN * 64) * 2 + (lane >> 4) * 16;
        const uint32_t b_rowl = (lane & 15) * B_STRIDE;

#pragma unroll
        for (int s = 0; s < 4; s++) {
            uint32_t afr[2][2][4];
#pragma unroll
            for (int mf = 0; mf < 2; mf++) {
                uint32_t base = buf + a_row + mf * (16 * A_STRIDE) + s * 32;
                ldm_x4(afr[mf][0], base + OFF_AH);
                ldm_x4(afr[mf][1], base + OFF_AL);
            }
            uint32_t bfr[4][2][4];
#pragma unroll
            for (int p = 0; p < 4; p++) {
                uint32_t base = buf + (uint32_t)(s * 16) * B_STRIDE + b_rowl
                              + b_col + p * 32;
                ldm_x4t(bfr[p][0], base + OFF_BH);
                ldm_x4t(bfr[p][1], base + OFF_BL);
            }
#pragma unroll
            for (int mf = 0; mf < 2; mf++)
#pragma unroll
                for (int p = 0; p < 4; p++)
#pragma unroll
                    for (int h = 0; h < 2; h++) {
                        float* c = acc[mf][p * 2 + h];
                        mma_bf16(c, afr[mf][0], &bfr[p][0][h * 2]);   // Ah*Bh
                        mma_bf16(c, afr[mf][0], &bfr[p][1][h * 2]);   // Ah*Bl
                        mma_bf16(c, afr[mf][1], &bfr[p][0][h * 2]);   // Al*Bh
                    }
        }
        __syncthreads();
        if (ch < 2) issue(ch + 2, ch & 1);
    }

#pragma unroll
    for (int mf = 0; mf < 2; mf++) {
        int mrow0 = m0g + warpM * 32 + mf * 16 + (lane >> 2);
        float b0 = bias[mrow0];
        float b1 = bias[mrow0 + 8];
        int ncol = n0 + warpN * 64 + (lane & 3) * 2;
#pragma unroll
        for (int nf = 0; nf < 8; nf++) {
            float* c = acc[mf][nf];
            float2 v0 = make_float2(c[0] + b0, c[1] + b0);
            float2 v1 = make_float2(c[2] + b1, c[3] + b1);
            *(float2*)&outp[(size_t)mrow0 * SPAT + ncol + nf * 8]       = v0;
            *(float2*)&outp[(size_t)(mrow0 + 8) * SPAT + ncol + nf * 8] = v1;
        }
    }
}

// ======== phase 1: softmax-attn*v -> w1+relu -> t[16], + sup prior ==========
// grid (256, 2branches), 256 threads; thread = one voxel.
__global__ __launch_bounds__(256)
void attn_t_kernel(const float* __restrict__ w1a, const float* __restrict__ b1a,
                   const float* __restrict__ w1b, const float* __restrict__ b1b,
                   const float* __restrict__ wsupa, const float* __restrict__ bsupa,
                   const float* __restrict__ wsupb, const float* __restrict__ bsupb,
                   float* __restrict__ sup1, float* __restrict__ sup2)
{
    __shared__ float w1s[16 * 128];
    __shared__ float wss[6 * 128];
    __shared__ float b1s[16];
    __shared__ float bss[6];

    const int br = blockIdx.y;
    const float* w1   = br ? w1b : w1a;
    const float* b1   = br ? b1b : b1a;
    const float* wsup = br ? wsupb : wsupa;
    const float* bsup = br ? bsupb : bsupa;
    const int nsup = br ? 1 : 6;
    float* sup_out = br ? sup2 : sup1;
    const int ch_off = br << 7;

    int tid = threadIdx.x;
    for (int i = tid; i < 2048; i += 256) w1s[i] = w1[i];
    for (int i = tid; i < nsup * 128; i += 256) wss[i] = wsup[i];
    if (tid < 16)   b1s[tid] = b1[tid];
    if (tid < nsup) bss[tid] = bsup[tid];
    __syncthreads();

    int vg = blockIdx.x * 256 + tid;   // global voxel (b,s), < 65536
    int b  = vg >> 15;
    int s  = vg & (SPAT - 1);
    size_t base = (size_t)b * CCH * SPAT + (size_t)ch_off * SPAT + s;

    float tacc[16];
#pragma unroll
    for (int j = 0; j < 16; j++) tacc[j] = 0.f;
    float supacc[6] = {0.f, 0.f, 0.f, 0.f, 0.f, 0.f};

#pragma unroll 1
    for (int h = 0; h < 8; h++) {
        float qv[16], ev[16], vv[16];
#pragma unroll
        for (int i = 0; i < 16; i++) {
            size_t a = base + (size_t)(h * 16 + i) * SPAT;
            qv[i] = g_q[a];
            float kv = g_k[a];
            vv[i] = g_v[a];
            ev[i] = qv[i] * kv * 0.25f;   // SCALE = HD^-0.5 = 0.25
        }
        float m = ev[0];
#pragma unroll
        for (int i = 1; i < 16; i++) m = fmaxf(m, ev[i]);
        float ssum = 0.f;
#pragma unroll
        for (int i = 0; i < 16; i++) { ev[i] = __expf(ev[i] - m); ssum += ev[i]; }
        float inv = 1.f / ssum;
#pragma unroll
        for (int i = 0; i < 16; i++) {
            float o = ev[i] * inv * vv[i];
            int c = h * 16 + i;
#pragma unroll
            for (int j = 0; j < 16; j++) tacc[j] += w1s[j * 128 + c] * o;
            for (int j = 0; j < nsup; j++) supacc[j] += wss[j * 128 + c] * qv[i];
        }
    }

    float* tp = &g_t[br * 1048576 + vg];
#pragma unroll
    for (int j = 0; j < 16; j++)
        tp[j * 65536] = fmaxf(tacc[j] + b1s[j], 0.f);

    size_t sbase = (size_t)b * nsup * SPAT + s;
    for (int j = 0; j < nsup; j++)
        sup_out[sbase + (size_t)j * SPAT] = supacc[j] + bss[j];
}

// ======== phase 2: out_s = sigmoid(W2 @ t + b2) =============================
// grid (128 chunks of 512 voxels, 2 branches), 256 threads; thread = 2 voxels.
__global__ __launch_bounds__(256)
void se2_kernel(const float* __restrict__ w2a, const float* __restrict__ b2a,
                const float* __restrict__ w2b, const float* __restrict__ b2b,
                float* __restrict__ out)
{
    __shared__ float ts[16 * 512];
    __shared__ float w2s[256 * 16];
    __shared__ float b2s[256];

    const int br = blockIdx.y;
    const float* w2 = br ? w2b : w2a;
    const float* b2 = br ? b2b : b2a;
    float* outp = out + (size_t)br * REG_SZ;

    const int tid = threadIdx.x;
    const int vg0 = blockIdx.x * 512;

    for (int i = tid; i < 4096; i += 256) w2s[i] = w2[i];
    b2s[tid] = b2[tid];
    const float* tg = &g_t[br * 1048576 + vg0];
#pragma unroll
    for (int t = 0; t < 32; t++) {
        int idx = tid + t * 256;            // 0..8191
        ts[idx] = tg[(idx >> 9) * 65536 + (idx & 511)];
    }
    __syncthreads();

    // register-resident t for this thread's two voxels
    float tv0[16], tv1[16];
#pragma unroll
    for (int j = 0; j < 16; j++) {
        tv0[j] = ts[j * 512 + tid];
        tv1[j] = ts[j * 512 + tid + 256];
    }

    const int vgA = vg0 + tid;
    const int bA = vgA >> 15, sA = vgA & (SPAT - 1);
    const int vgB = vg0 + tid + 256;
    const int bB = vgB >> 15, sB = vgB & (SPAT - 1);
    float* oA = outp + (size_t)bA * CCH * SPAT + sA;
    float* oB = outp + (size_t)bB * CCH * SPAT + sB;

#pragma unroll 8
    for (int o = 0; o < 256; o++) {
        const float* w = &w2s[o * 16];
        float a0 = b2s[o], a1 = b2s[o];
#pragma unroll
        for (int j = 0; j < 16; j++) {
            float wv = w[j];
            a0 += wv * tv0[j];
            a1 += wv * tv1[j];
        }
        oA[(size_t)o * SPAT] = 1.f / (1.f + __expf(-a0));
        oB[(size_t)o * SPAT] = 1.f / (1.f + __expf(-a1));
    }
}

// ---------------- deterministic max/mean/min pooling ------------------------
__global__ __launch_bounds__(256)
void pool_kernel(const float* __restrict__ outbase)
{
    __shared__ float smx[256], smn[256], ssm[256];
    int blk = blockIdx.x;        // 0..1023 : region*512 + b*256 + c
    int r   = blk >> 9;
    int bc  = blk & 511;
    const float* p = outbase + (size_t)r * REG_SZ + (size_t)bc * SPAT;
    int tid = threadIdx.x;
    float mx = -1e30f, mn = 1e30f, sm = 0.f;
    for (int i = tid; i < SPAT; i += 256) {
        float v = p[i];
        mx = fmaxf(mx, v); mn = fminf(mn, v); sm += v;
    }
    smx[tid] = mx; smn[tid] = mn; ssm[tid] = sm;
    __syncthreads();
    for (int st = 128; st > 0; st >>= 1) {
        if (tid < st) {
            smx[tid] = fmaxf(smx[tid], smx[tid + st]);
            smn[tid] = fminf(smn[tid], smn[tid + st]);
            ssm[tid] += ssm[tid + st];
        }
        __syncthreads();
    }
    if (tid == 0) {
        g_pool[blk * 3 + 0] = smx[0];
        g_pool[blk * 3 + 1] = ssm[0] * (1.f / 32768.f);
        g_pool[blk * 3 + 2] = smn[0];
    }
}

// ---------------- gate: Conv1d(3->1) + FC squeeze-excite --------------------
__global__ __launch_bounds__(256)
void gate_kernel(const float* __restrict__ sq1w, const float* __restrict__ sq1b,
                 const float* __restrict__ sq2w, const float* __restrict__ sq2b,
                 const float* __restrict__ f1w1, const float* __restrict__ f1b1,
                 const float* __restrict__ f1w2, const float* __restrict__ f1b2,
                 const float* __restrict__ f2w1, const float* __restrict__ f2b1,
                 const float* __restrict__ f2w2, const float* __restrict__ f2b2)
{
    int r = blockIdx.x >> 1, b = blockIdx.x & 1;
    const float* sqw = r ? sq2w : sq1w;
    const float* sqb = r ? sq2b : sq1b;
    const float* fw1 = r ? f2w1 : f1w1;
    const float* fb1 = r ? f2b1 : f1b1;
    const float* fw2 = r ? f2w2 : f1w2;
    const float* fb2 = r ? f2b2 : f1b2;

    __shared__ float sqs[256], hs[16];
    int c = threadIdx.x;
    const float* pr = &g_pool[(r * 512 + b * 256 + c) * 3];
    sqs[c] = pr[0] * sqw[0] + pr[1] * sqw[1] + pr[2] * sqw[2] + sqb[0];
    __syncthreads();
    if (c < 16) {
        float a = fb1[c];
        for (int j = 0; j < 256; j++) a += fw1[c * 256 + j] * sqs[j];
        hs[c] = fmaxf(a, 0.f);
    }
    __syncthreads();
    float a = fb2[c];
#pragma unroll
    for (int j = 0; j < 16; j++) a += fw2[c * 16 + j] * hs[j];
    g_gate[r * 512 + b * 256 + c] = 1.f / (1.f + __expf(-a));
}

// ---------------- apply gate in place on out1|out2 --------------------------
__global__ __launch_bounds__(256)
void scale_kernel(float* __restrict__ out)
{
    size_t i = (size_t)blockIdx.x * 256 + threadIdx.x;  // float4 index, < 8388608
    int r  = (int)(i >> 22);            // 4194304 float4 per region
    int bc = (int)((i >> 13) & 511);    // 8192 float4 per (b,c) row
    float g = g_gate[r * 512 + bc];
    float4* p = ((float4*)out) + i;
    float4 v = *p;
    v.x *= g; v.y *= g; v.z *= g; v.w *= g;
    *p = v;
}

// ---------------- launch ----------------------------------------------------
extern "C" void kernel_launch(void* const* d_in, const int* in_sizes, int n_in,
                              void* d_out, int out_size)
{
    const float* x      = (const float*)d_in[0];
    const float* Wq     = (const float*)d_in[1];
    const float* bq     = (const float*)d_in[2];
    const float* Wk     = (const float*)d_in[3];
    const float* bk     = (const float*)d_in[4];
    const float* Wv     = (const float*)d_in[5];
    const float* bv     = (const float*)d_in[6];
    const float* Wq1p   = (const float*)d_in[7];
    const float* bq1p   = (const float*)d_in[8];
    const float* Wq2p   = (const float*)d_in[9];
    const float* bq2p   = (const float*)d_in[10];
    const float* sq1_w  = (const float*)d_in[11];
    const float* sq1_b  = (const float*)d_in[12];
    const float* sq2_w  = (const float*)d_in[13];
    const float* sq2_b  = (const float*)d_in[14];
    const float* se1_w1 = (const float*)d_in[15];
    const float* se1_b1 = (const float*)d_in[16];
    const float* se1_w2 = (const float*)d_in[17];
    const float* se1_b2 = (const float*)d_in[18];
    const float* se2_w1 = (const float*)d_in[19];
    const float* se2_b1 = (const float*)d_in[20];
    const float* se2_w2 = (const float*)d_in[21];
    const float* se2_b2 = (const float*)d_in[22];
    const float* sec1_w1 = (const float*)d_in[23];
    const float* sec1_b1 = (const float*)d_in[24];
    const float* sec1_w2 = (const float*)d_in[25];
    const float* sec1_b2 = (const float*)d_in[26];
    const float* sec2_w1 = (const float*)d_in[27];
    const float* sec2_b1 = (const float*)d_in[28];
    const float* sec2_w2 = (const float*)d_in[29];
    const float* sec2_b2 = (const float*)d_in[30];

    float* out  = (float*)d_out;
    float* sup1 = out + (size_t)2 * REG_SZ;        // 33554432
    float* sup2 = sup1 + 2 * 6 * SPAT;             // 33947648

    convert_x<<<16384, 256>>>(x);
    dim3 gw(64, 3);
    convert_w<<<gw, 256>>>(Wq, Wk, Wv);

    cudaFuncSetAttribute(qkv_gemm_mma, cudaFuncAttributeMaxDynamicSharedMemorySize,
                         GEMM_SMEM);
    dim3 gg(256, 2, 6);   // ntiles, mtiles, mat*2+batch
    qkv_gemm_mma<<<gg, 256, GEMM_SMEM>>>(bq, bk, bv);

    dim3 ga(256, 2);
    attn_t_kernel<<<ga, 256>>>(se1_w1, se1_b1, se2_w1, se2_b1,
                               Wq1p, bq1p, Wq2p, bq2p, sup1, sup2);

    dim3 gs(128, 2);
    se2_kernel<<<gs, 256>>>(se1_w2, se1_b2, se2_w2, se2_b2, out);

    pool_kernel<<<1024, 256>>>(out);

    gate_kernel<<<4, 256>>>(sq1_w, sq1_b, sq2_w, sq2_b,
                            sec1_w1, sec1_b1, sec1_w2, sec1_b2,
                            sec2_w1, sec2_b1, sec2_w2, sec2_b2);

    scale_kernel<<<32768, 256>>>(out);
}

// round 6
// speedup vs baseline: 1.9317x; 1.0576x over previous
#include <cuda_runtime.h>
#include <cuda_bf16.h>
#include <math.h>
#include <stdint.h>

#define SPAT 32768           // D*H*W
#define CCH  256             // channels
#define REG_SZ (2*256*32768) // one region (b, 256, 32768)

// ---------------- scratch (device globals; no allocations allowed) ----------
__device__ float g_q[REG_SZ];
__device__ float g_k[REG_SZ];
__device__ float g_v[REG_SZ];
__device__ float g_t[2 * 16 * 65536];       // [branch][j][b*32768+s]
__device__ __nv_bfloat16 g_xh[REG_SZ];      // x hi bf16
__device__ __nv_bfloat16 g_xl[REG_SZ];      // x lo bf16
__device__ __nv_bfloat16 g_wh[3 * 256 * 256];
__device__ __nv_bfloat16 g_wl[3 * 256 * 256];
__device__ float g_pool[2 * 512 * 3];   // [region][b*256+c][max,avg,min]
__device__ float g_gate[2 * 512];       // [region][b*256+c]

// ======================= helpers ============================================
__device__ __forceinline__ uint32_t smem_u32(const void* p) {
    uint32_t a;
    asm("{ .reg .u64 t; cvta.to.shared.u64 t, %1; cvt.u32.u64 %0, t; }"
        : "=r"(a) : "l"(p));
    return a;
}
__device__ __forceinline__ void cp16(uint32_t dst, const void* src) {
    asm volatile("cp.async.cg.shared.global [%0], [%1], 16;"
                 :: "r"(dst), "l"(src) : "memory");
}
#define CP_COMMIT() asm volatile("cp.async.commit_group;" ::: "memory")
#define CP_WAIT(n)  asm volatile("cp.async.wait_group %0;" :: "n"(n) : "memory")

__device__ __forceinline__ void ldm_x4(uint32_t* r, uint32_t a) {
    asm volatile("ldmatrix.sync.aligned.m8n8.x4.shared.b16 {%0,%1,%2,%3}, [%4];"
        : "=r"(r[0]), "=r"(r[1]), "=r"(r[2]), "=r"(r[3]) : "r"(a));
}
__device__ __forceinline__ void ldm_x4t(uint32_t* r, uint32_t a) {
    asm volatile("ldmatrix.sync.aligned.m8n8.x4.trans.shared.b16 {%0,%1,%2,%3}, [%4];"
        : "=r"(r[0]), "=r"(r[1]), "=r"(r[2]), "=r"(r[3]) : "r"(a));
}
__device__ __forceinline__ void mma_bf16(float* c, const uint32_t* a, const uint32_t* b) {
    asm volatile(
        "mma.sync.aligned.m16n8k16.row.col.f32.bf16.bf16.f32 "
        "{%0,%1,%2,%3}, {%4,%5,%6,%7}, {%8,%9}, {%0,%1,%2,%3};"
        : "+f"(c[0]), "+f"(c[1]), "+f"(c[2]), "+f"(c[3])
        : "r"(a[0]), "r"(a[1]), "r"(a[2]), "r"(a[3]), "r"(b[0]), "r"(b[1]));
}

// ---------------- pre-convert: fp32 -> bf16 hi/lo ---------------------------
__device__ __forceinline__ void split4_pack(float4 v, uint2& h, uint2& l) {
    __nv_bfloat16 hx = __float2bfloat16_rn(v.x), hy = __float2bfloat16_rn(v.y);
    __nv_bfloat16 hz = __float2bfloat16_rn(v.z), hw = __float2bfloat16_rn(v.w);
    __nv_bfloat16 lx = __float2bfloat16_rn(v.x - __bfloat162float(hx));
    __nv_bfloat16 ly = __float2bfloat16_rn(v.y - __bfloat162float(hy));
    __nv_bfloat16 lz = __float2bfloat16_rn(v.z - __bfloat162float(hz));
    __nv_bfloat16 lw = __float2bfloat16_rn(v.w - __bfloat162float(hw));
    h.x = (uint32_t)__bfloat16_as_ushort(hx) | ((uint32_t)__bfloat16_as_ushort(hy) << 16);
    h.y = (uint32_t)__bfloat16_as_ushort(hz) | ((uint32_t)__bfloat16_as_ushort(hw) << 16);
    l.x = (uint32_t)__bfloat16_as_ushort(lx) | ((uint32_t)__bfloat16_as_ushort(ly) << 16);
    l.y = (uint32_t)__bfloat16_as_ushort(lz) | ((uint32_t)__bfloat16_as_ushort(lw) << 16);
}

__global__ __launch_bounds__(256)
void convert_x(const float* __restrict__ x)
{
    size_t i = (size_t)blockIdx.x * 256 + threadIdx.x;   // float4 idx, < 4194304
    float4 v = ((const float4*)x)[i];
    uint2 h, l; split4_pack(v, h, l);
    *(uint2*)&g_xh[i * 4] = h;
    *(uint2*)&g_xl[i * 4] = l;
}

__global__ __launch_bounds__(256)
void convert_w(const float* __restrict__ Wq, const float* __restrict__ Wk,
               const float* __restrict__ Wv)
{
    int mat = blockIdx.y;
    const float* W = (mat == 0) ? Wq : ((mat == 1) ? Wk : Wv);
    size_t i = (size_t)blockIdx.x * 256 + threadIdx.x;   // float4 idx, < 16384
    float4 v = ((const float4*)W)[i];
    uint2 h, l; split4_pack(v, h, l);
    *(uint2*)&g_wh[(size_t)mat * 65536 + i * 4] = h;
    *(uint2*)&g_wl[(size_t)mat * 65536 + i * 4] = l;
}

// ---------------- SMEM layout (per buffer, 108544 B; double buffered) -------
// A (W tile): 256 rows x 64 k bf16, row stride 144 B -> 36864 B per sel
// B (X tile): 64 rows(k) x 128 n bf16, row stride 272 B -> 17408 B per sel
#define A_STRIDE 144
#define B_STRIDE 272
#define OFF_AH 0
#define OFF_AL 36864
#define OFF_BH 73728
#define OFF_BL 91136
#define BUF_SZ 108544
#define GEMM_SMEM (2 * BUF_SZ)   // 217088

// ================== mma.sync QKV GEMM (cp.async bf16, M=256/CTA) ============
// grid: (256 ntiles, 6 = mat*2+batch); 256 threads (8 warps: 4 warpM x 2 warpN)
// each warpM covers 64 M-rows (4 mf-fragments of 16).
__global__ __launch_bounds__(256, 1)
void qkv_gemm_mma(const float* __restrict__ bq, const float* __restrict__ bk,
                  const float* __restrict__ bv)
{
    extern __shared__ char sm[];
    const uint32_t smb = smem_u32(sm);

    const int tid   = threadIdx.x;
    const int warp  = tid >> 5, lane = tid & 31;
    const int warpM = warp >> 1, warpN = warp & 1;
    const int n0    = blockIdx.x * 128;
    const int mat   = blockIdx.y >> 1, bb = blockIdx.y & 1;

    const float* bias = (mat == 0) ? bq : ((mat == 1) ? bk : bv);
    float* outp = ((mat == 0) ? g_q : ((mat == 1) ? g_k : g_v))
                  + (size_t)bb * CCH * SPAT;
    const __nv_bfloat16* Wh = g_wh + (size_t)mat * 65536;
    const __nv_bfloat16* Wl = g_wl + (size_t)mat * 65536;
    const __nv_bfloat16* Xh = g_xh + (size_t)bb * CCH * SPAT + n0;
    const __nv_bfloat16* Xl = g_xl + (size_t)bb * CCH * SPAT + n0;

    auto issue = [&](int ch, int buf) {
        const uint32_t base = smb + buf * BUF_SZ;
        const int kc0 = ch << 6;
#pragma unroll
        for (int t = 0; t < 8; t++) {
            int idx = tid + t * 256;           // 0..2047
            int row = idx >> 3, piece = idx & 7;
            uint32_t doff = (uint32_t)row * A_STRIDE + piece * 16;
            size_t soff = (size_t)row * 256 + kc0 + piece * 8;
            cp16(base + OFF_AH + doff, Wh + soff);
            cp16(base + OFF_AL + doff, Wl + soff);
        }
#pragma unroll
        for (int t = 0; t < 4; t++) {
            int idx = tid + t * 256;           // 0..1023
            int row = idx >> 4, piece = idx & 15;
            uint32_t doff = (uint32_t)row * B_STRIDE + piece * 16;
            size_t soff = (size_t)(kc0 + row) * SPAT + piece * 8;
            cp16(base + OFF_BH + doff, Xh + soff);
            cp16(base + OFF_BL + doff, Xl + soff);
        }
        CP_COMMIT();
    };

    float acc[4][8][4];
#pragma unroll
    for (int i = 0; i < 4; i++)
#pragma unroll
        for (int j = 0; j < 8; j++)
#pragma unroll
            for (int c = 0; c < 4; c++) acc[i][j][c] = 0.f;

    issue(0, 0);
    issue(1, 1);

#pragma unroll 1
    for (int ch = 0; ch < 4; ch++) {
        if (ch < 3) { CP_WAIT(1); } else { CP_WAIT(0); }
        __syncthreads();

        const uint32_t buf = smb + (ch & 1) * BUF_SZ;
        const uint32_t a_rowb = (warpM * 64 + (lane & 15)) * A_STRIDE + (lane >> 4) * 16;
        const uint32_t b_col  = (warpN * 64) * 2 + (lane >> 4) * 16;
        const uint32_t b_rowl = (lane & 15) * B_STRIDE;

#pragma unroll
        for (int s = 0; s < 4; s++) {
            uint32_t bfr[4][2][4];
#pragma unroll
            for (int p = 0; p < 4; p++) {
                uint32_t base = buf + (uint32_t)(s * 16) * B_STRIDE + b_rowl
                              + b_col + p * 32;
                ldm_x4t(bfr[p][0], base + OFF_BH);
                ldm_x4t(bfr[p][1], base + OFF_BL);
            }
#pragma unroll
            for (int mf = 0; mf < 4; mf++) {
                uint32_t afr[2][4];
                uint32_t abase = buf + a_rowb + mf * (16 * A_STRIDE) + s * 32;
                ldm_x4(afr[0], abase + OFF_AH);
                ldm_x4(afr[1], abase + OFF_AL);
#pragma unroll
                for (int p = 0; p < 4; p++)
#pragma unroll
                    for (int h = 0; h < 2; h++) {
                        float* c = acc[mf][p * 2 + h];
                        mma_bf16(c, afr[0], &bfr[p][0][h * 2]);   // Ah*Bh
                        mma_bf16(c, afr[0], &bfr[p][1][h * 2]);   // Ah*Bl
                        mma_bf16(c, afr[1], &bfr[p][0][h * 2]);   // Al*Bh
                    }
            }
        }
        __syncthreads();
        if (ch < 2) issue(ch + 2, ch & 1);
    }

#pragma unroll
    for (int mf = 0; mf < 4; mf++) {
        int mrow0 = warpM * 64 + mf * 16 + (lane >> 2);
        float b0 = bias[mrow0];
        float b1 = bias[mrow0 + 8];
        int ncol = n0 + warpN * 64 + (lane & 3) * 2;
#pragma unroll
        for (int nf = 0; nf < 8; nf++) {
            float* c = acc[mf][nf];
            float2 v0 = make_float2(c[0] + b0, c[1] + b0);
            float2 v1 = make_float2(c[2] + b1, c[3] + b1);
            *(float2*)&outp[(size_t)mrow0 * SPAT + ncol + nf * 8]       = v0;
            *(float2*)&outp[(size_t)(mrow0 + 8) * SPAT + ncol + nf * 8] = v1;
        }
    }
}

// ======== phase 1: softmax-attn*v -> w1+relu -> t[16], + sup prior ==========
// grid 512 blocks x 128 threads per branch; thread = one voxel.
template <int NSUP>
__global__ __launch_bounds__(128)
void attn_t_kernel(int br,
                   const float* __restrict__ w1,  const float* __restrict__ b1,
                   const float* __restrict__ wsup, const float* __restrict__ bsup,
                   float* __restrict__ sup_out)
{
    __shared__ float w1s[16 * 128];
    __shared__ float wss[NSUP * 128];
    __shared__ float b1s[16];
    __shared__ float bss[NSUP];

    const int ch_off = br << 7;
    int tid = threadIdx.x;
    for (int i = tid; i < 2048; i += 128) w1s[i] = w1[i];
    for (int i = tid; i < NSUP * 128; i += 128) wss[i] = wsup[i];
    if (tid < 16)   b1s[tid] = b1[tid];
    if (tid < NSUP) bss[tid] = bsup[tid];
    __syncthreads();

    int vg = blockIdx.x * 128 + tid;   // global voxel (b,s), < 65536
    int b  = vg >> 15;
    int s  = vg & (SPAT - 1);
    size_t base = (size_t)b * CCH * SPAT + (size_t)ch_off * SPAT + s;

    float tacc[16];
#pragma unroll
    for (int j = 0; j < 16; j++) tacc[j] = 0.f;
    float supacc[NSUP];
#pragma unroll
    for (int j = 0; j < NSUP; j++) supacc[j] = 0.f;

#pragma unroll 1
    for (int h = 0; h < 8; h++) {
        float qv[16], ev[16], vv[16];
#pragma unroll
        for (int i = 0; i < 16; i++) {
            size_t a = base + (size_t)(h * 16 + i) * SPAT;
            qv[i] = g_q[a];
            float kv = g_k[a];
            vv[i] = g_v[a];
            ev[i] = qv[i] * kv * 0.25f;   // SCALE = HD^-0.5 = 0.25
        }
        float m = ev[0];
#pragma unroll
        for (int i = 1; i < 16; i++) m = fmaxf(m, ev[i]);
        float ssum = 0.f;
#pragma unroll
        for (int i = 0; i < 16; i++) { ev[i] = __expf(ev[i] - m); ssum += ev[i]; }
        float inv = 1.f / ssum;
#pragma unroll
        for (int i = 0; i < 16; i++) {
            float o = ev[i] * inv * vv[i];
            int c = h * 16 + i;
#pragma unroll
            for (int j = 0; j < 16; j++) tacc[j] += w1s[j * 128 + c] * o;
#pragma unroll
            for (int j = 0; j < NSUP; j++) supacc[j] += wss[j * 128 + c] * qv[i];
        }
    }

    float* tp = &g_t[br * 1048576 + vg];
#pragma unroll
    for (int j = 0; j < 16; j++)
        tp[j * 65536] = fmaxf(tacc[j] + b1s[j], 0.f);

    size_t sbase = (size_t)b * NSUP * SPAT + s;
#pragma unroll
    for (int j = 0; j < NSUP; j++)
        sup_out[sbase + (size_t)j * SPAT] = supacc[j] + bss[j];
}

// ======== phase 2: out_s = sigmoid(W2 @ t + b2) =============================
// grid (256 chunks of 256 voxels, 2 branches), 128 threads; thread = 2 voxels.
__global__ __launch_bounds__(128)
void se2_kernel(const float* __restrict__ w2a, const float* __restrict__ b2a,
                const float* __restrict__ w2b, const float* __restrict__ b2b,
                float* __restrict__ out)
{
    __shared__ float ts[16 * 256];
    __shared__ float w2s[256 * 16];
    __shared__ float b2s[256];

    const int br = blockIdx.y;
    const float* w2 = br ? w2b : w2a;
    const float* b2 = br ? b2b : b2a;
    float* outp = out + (size_t)br * REG_SZ;

    const int tid = threadIdx.x;
    const int vg0 = blockIdx.x * 256;

#pragma unroll
    for (int t = 0; t < 32; t++) w2s[tid + t * 128] = w2[tid + t * 128];
    b2s[tid] = b2[tid];
    b2s[tid + 128] = b2[tid + 128];
    const float* tg = &g_t[br * 1048576 + vg0];
#pragma unroll
    for (int t = 0; t < 32; t++) {
        int idx = tid + t * 128;            // 0..4095
        ts[idx] = tg[(idx >> 8) * 65536 + (idx & 255)];
    }
    __syncthreads();

    float tv0[16], tv1[16];
#pragma unroll
    for (int j = 0; j < 16; j++) {
        tv0[j] = ts[j * 256 + tid];
        tv1[j] = ts[j * 256 + tid + 128];
    }

    const int vgA = vg0 + tid;
    const int bA = vgA >> 15, sA = vgA & (SPAT - 1);
    const int vgB = vg0 + tid + 128;
    const int bB = vgB >> 15, sB = vgB & (SPAT - 1);
    float* oA = outp + (size_t)bA * CCH * SPAT + sA;
    float* oB = outp + (size_t)bB * CCH * SPAT + sB;

#pragma unroll 8
    for (int o = 0; o < 256; o++) {
        const float* w = &w2s[o * 16];
        float a0 = b2s[o], a1 = b2s[o];
#pragma unroll
        for (int j = 0; j < 16; j++) {
            float wv = w[j];
            a0 += wv * tv0[j];
            a1 += wv * tv1[j];
        }
        oA[(size_t)o * SPAT] = 1.f / (1.f + __expf(-a0));
        oB[(size_t)o * SPAT] = 1.f / (1.f + __expf(-a1));
    }
}

// ---------------- deterministic max/mean/min pooling (float4) ---------------
__global__ __launch_bounds__(256)
void pool_kernel(const float* __restrict__ outbase)
{
    __shared__ float smx[256], smn[256], ssm[256];
    int blk = blockIdx.x;        // 0..1023 : region*512 + b*256 + c
    int r   = blk >> 9;
    int bc  = blk & 511;
    const float4* p = (const float4*)(outbase + (size_t)r * REG_SZ + (size_t)bc * SPAT);
    int tid = threadIdx.x;
    float mx = -1e30f, mn = 1e30f, sm = 0.f;
#pragma unroll 4
    for (int i = tid; i < SPAT / 4; i += 256) {
        float4 v = p[i];
        mx = fmaxf(mx, fmaxf(fmaxf(v.x, v.y), fmaxf(v.z, v.w)));
        mn = fminf(mn, fminf(fminf(v.x, v.y), fminf(v.z, v.w)));
        sm += (v.x + v.y) + (v.z + v.w);
    }
    smx[tid] = mx; smn[tid] = mn; ssm[tid] = sm;
    __syncthreads();
    for (int st = 128; st > 0; st >>= 1) {
        if (tid < st) {
            smx[tid] = fmaxf(smx[tid], smx[tid + st]);
            smn[tid] = fminf(smn[tid], smn[tid + st]);
            ssm[tid] += ssm[tid + st];
        }
        __syncthreads();
    }
    if (tid == 0) {
        g_pool[blk * 3 + 0] = smx[0];
        g_pool[blk * 3 + 1] = ssm[0] * (1.f / 32768.f);
        g_pool[blk * 3 + 2] = smn[0];
    }
}

// ---------------- gate: Conv1d(3->1) + FC squeeze-excite --------------------
__global__ __launch_bounds__(256)
void gate_kernel(const float* __restrict__ sq1w, const float* __restrict__ sq1b,
                 const float* __restrict__ sq2w, const float* __restrict__ sq2b,
                 const float* __restrict__ f1w1, const float* __restrict__ f1b1,
                 const float* __restrict__ f1w2, const float* __restrict__ f1b2,
                 const float* __restrict__ f2w1, const float* __restrict__ f2b1,
                 const float* __restrict__ f2w2, const float* __restrict__ f2b2)
{
    int r = blockIdx.x >> 1, b = blockIdx.x & 1;
    const float* sqw = r ? sq2w : sq1w;
    const float* sqb = r ? sq2b : sq1b;
    const float* fw1 = r ? f2w1 : f1w1;
    const float* fb1 = r ? f2b1 : f1b1;
    const float* fw2 = r ? f2w2 : f1w2;
    const float* fb2 = r ? f2b2 : f1b2;

    __shared__ float sqs[256], hs[16];
    int c = threadIdx.x;
    const float* pr = &g_pool[(r * 512 + b * 256 + c) * 3];
    sqs[c] = pr[0] * sqw[0] + pr[1] * sqw[1] + pr[2] * sqw[2] + sqb[0];
    __syncthreads();
    if (c < 16) {
        float a = fb1[c];
        for (int j = 0; j < 256; j++) a += fw1[c * 256 + j] * sqs[j];
        hs[c] = fmaxf(a, 0.f);
    }
    __syncthreads();
    float a = fb2[c];
#pragma unroll
    for (int j = 0; j < 16; j++) a += fw2[c * 16 + j] * hs[j];
    g_gate[r * 512 + b * 256 + c] = 1.f / (1.f + __expf(-a));
}

// ======== final: out = gate * sigmoid(W2 @ t + b2), recomputed from t =======
// grid (512, 2), 128 threads; thread = one voxel. Write-only 268MB.
__global__ __launch_bounds__(128)
void final_kernel(const float* __restrict__ w2a, const float* __restrict__ b2a,
                  const float* __restrict__ w2b, const float* __restrict__ b2b,
                  float* __restrict__ out)
{
    __shared__ float w2s[256 * 16];
    __shared__ float b2s[256];
    __shared__ float gs[256];

    const int br = blockIdx.y;
    const float* w2 = br ? w2b : w2a;
    const float* b2 = br ? b2b : b2a;
    float* outp = out + (size_t)br * REG_SZ;

    const int tid = threadIdx.x;
    const int vg0 = blockIdx.x * 128;
    const int b   = vg0 >> 15;            // constant per block

#pragma unroll
    for (int t = 0; t < 32; t++) w2s[tid + t * 128] = w2[tid + t * 128];
    b2s[tid] = b2[tid];
    b2s[tid + 128] = b2[tid + 128];
    gs[tid] = g_gate[br * 512 + b * 256 + tid];
    gs[tid + 128] = g_gate[br * 512 + b * 256 + tid + 128];

    const int vg = vg0 + tid;
    const int s  = vg & (SPAT - 1);
    float tv[16];
    const float* tg = &g_t[br * 1048576 + vg];
#pragma unroll
    for (int j = 0; j < 16; j++) tv[j] = tg[j * 65536];
    __syncthreads();

    float* op = outp + (size_t)b * CCH * SPAT + s;
#pragma unroll 8
    for (int o = 0; o < 256; o++) {
        const float* w = &w2s[o * 16];
        float a = b2s[o];
#pragma unroll
        for (int j = 0; j < 16; j++) a += w[j] * tv[j];
        op[(size_t)o * SPAT] = gs[o] / (1.f + __expf(-a));
    }
}

// ---------------- launch ----------------------------------------------------
extern "C" void kernel_launch(void* const* d_in, const int* in_sizes, int n_in,
                              void* d_out, int out_size)
{
    const float* x      = (const float*)d_in[0];
    const float* Wq     = (const float*)d_in[1];
    const float* bq     = (const float*)d_in[2];
    const float* Wk     = (const float*)d_in[3];
    const float* bk     = (const float*)d_in[4];
    const float* Wv     = (const float*)d_in[5];
    const float* bv     = (const float*)d_in[6];
    const float* Wq1p   = (const float*)d_in[7];
    const float* bq1p   = (const float*)d_in[8];
    const float* Wq2p   = (const float*)d_in[9];
    const float* bq2p   = (const float*)d_in[10];
    const float* sq1_w  = (const float*)d_in[11];
    const float* sq1_b  = (const float*)d_in[12];
    const float* sq2_w  = (const float*)d_in[13];
    const float* sq2_b  = (const float*)d_in[14];
    const float* se1_w1 = (const float*)d_in[15];
    const float* se1_b1 = (const float*)d_in[16];
    const float* se1_w2 = (const float*)d_in[17];
    const float* se1_b2 = (const float*)d_in[18];
    const float* se2_w1 = (const float*)d_in[19];
    const float* se2_b1 = (const float*)d_in[20];
    const float* se2_w2 = (const float*)d_in[21];
    const float* se2_b2 = (const float*)d_in[22];
    const float* sec1_w1 = (const float*)d_in[23];
    const float* sec1_b1 = (const float*)d_in[24];
    const float* sec1_w2 = (const float*)d_in[25];
    const float* sec1_b2 = (const float*)d_in[26];
    const float* sec2_w1 = (const float*)d_in[27];
    const float* sec2_b1 = (const float*)d_in[28];
    const float* sec2_w2 = (const float*)d_in[29];
    const float* sec2_b2 = (const float*)d_in[30];

    float* out  = (float*)d_out;
    float* sup1 = out + (size_t)2 * REG_SZ;        // 33554432
    float* sup2 = sup1 + 2 * 6 * SPAT;             // 33947648

    convert_x<<<16384, 256>>>(x);
    dim3 gw(64, 3);
    convert_w<<<gw, 256>>>(Wq, Wk, Wv);

    cudaFuncSetAttribute(qkv_gemm_mma, cudaFuncAttributeMaxDynamicSharedMemorySize,
                         GEMM_SMEM);
    dim3 gg(256, 6);   // ntiles, mat*2+batch
    qkv_gemm_mma<<<gg, 256, GEMM_SMEM>>>(bq, bk, bv);

    attn_t_kernel<6><<<512, 128>>>(0, se1_w1, se1_b1, Wq1p, bq1p, sup1);
    attn_t_kernel<1><<<512, 128>>>(1, se2_w1, se2_b1, Wq2p, bq2p, sup2);

    dim3 gs(256, 2);
    se2_kernel<<<gs, 128>>>(se1_w2, se1_b2, se2_w2, se2_b2, out);

    pool_kernel<<<1024, 256>>>(out);

    gate_kernel<<<4, 256>>>(sq1_w, sq1_b, sq2_w, sq2_b,
                            sec1_w1, sec1_b1, sec1_w2, sec1_b2,
                            sec2_w1, sec2_b1, sec2_w2, sec2_b2);

    dim3 gf(512, 2);
    final_kernel<<<gf, 128>>>(se1_w2, se1_b2, se2_w2, se2_b2, out);
}

// round 7
// speedup vs baseline: 1.9579x; 1.0136x over previous
#include <cuda_runtime.h>
#include <cuda_bf16.h>
#include <math.h>
#include <stdint.h>

#define SPAT 32768           // D*H*W
#define CCH  256             // channels
#define REG_SZ (2*256*32768) // one region (b, 256, 32768)

// ---------------- scratch (device globals; no allocations allowed) ----------
__device__ float g_q[REG_SZ];
__device__ float g_k[REG_SZ];
__device__ float g_v[REG_SZ];
__device__ float g_t[2 * 16 * 65536];       // [branch][j][b*32768+s]
__device__ __nv_bfloat16 g_xh[REG_SZ];      // x hi bf16
__device__ __nv_bfloat16 g_xl[REG_SZ];      // x lo bf16
__device__ __nv_bfloat16 g_wh[3 * 256 * 256];
__device__ __nv_bfloat16 g_wl[3 * 256 * 256];
__device__ float g_pool[2 * 512 * 3];   // [region][b*256+c][max,avg,min]
__device__ float g_gate[2 * 512];       // [region][b*256+c]

// ======================= helpers ============================================
__device__ __forceinline__ uint32_t smem_u32(const void* p) {
    uint32_t a;
    asm("{ .reg .u64 t; cvta.to.shared.u64 t, %1; cvt.u32.u64 %0, t; }"
        : "=r"(a) : "l"(p));
    return a;
}
__device__ __forceinline__ void cp16(uint32_t dst, const void* src) {
    asm volatile("cp.async.cg.shared.global [%0], [%1], 16;"
                 :: "r"(dst), "l"(src) : "memory");
}
#define CP_COMMIT() asm volatile("cp.async.commit_group;" ::: "memory")
#define CP_WAIT(n)  asm volatile("cp.async.wait_group %0;" :: "n"(n) : "memory")

__device__ __forceinline__ void ldm_x4(uint32_t* r, uint32_t a) {
    asm volatile("ldmatrix.sync.aligned.m8n8.x4.shared.b16 {%0,%1,%2,%3}, [%4];"
        : "=r"(r[0]), "=r"(r[1]), "=r"(r[2]), "=r"(r[3]) : "r"(a));
}
__device__ __forceinline__ void ldm_x4t(uint32_t* r, uint32_t a) {
    asm volatile("ldmatrix.sync.aligned.m8n8.x4.trans.shared.b16 {%0,%1,%2,%3}, [%4];"
        : "=r"(r[0]), "=r"(r[1]), "=r"(r[2]), "=r"(r[3]) : "r"(a));
}
__device__ __forceinline__ void mma_bf16(float* c, const uint32_t* a, const uint32_t* b) {
    asm volatile(
        "mma.sync.aligned.m16n8k16.row.col.f32.bf16.bf16.f32 "
        "{%0,%1,%2,%3}, {%4,%5,%6,%7}, {%8,%9}, {%0,%1,%2,%3};"
        : "+f"(c[0]), "+f"(c[1]), "+f"(c[2]), "+f"(c[3])
        : "r"(a[0]), "r"(a[1]), "r"(a[2]), "r"(a[3]), "r"(b[0]), "r"(b[1]));
}

// ---------------- pre-convert: fp32 -> bf16 hi/lo ---------------------------
__device__ __forceinline__ void split4_pack(float4 v, uint2& h, uint2& l) {
    __nv_bfloat16 hx = __float2bfloat16_rn(v.x), hy = __float2bfloat16_rn(v.y);
    __nv_bfloat16 hz = __float2bfloat16_rn(v.z), hw = __float2bfloat16_rn(v.w);
    __nv_bfloat16 lx = __float2bfloat16_rn(v.x - __bfloat162float(hx));
    __nv_bfloat16 ly = __float2bfloat16_rn(v.y - __bfloat162float(hy));
    __nv_bfloat16 lz = __float2bfloat16_rn(v.z - __bfloat162float(hz));
    __nv_bfloat16 lw = __float2bfloat16_rn(v.w - __bfloat162float(hw));
    h.x = (uint32_t)__bfloat16_as_ushort(hx) | ((uint32_t)__bfloat16_as_ushort(hy) << 16);
    h.y = (uint32_t)__bfloat16_as_ushort(hz) | ((uint32_t)__bfloat16_as_ushort(hw) << 16);
    l.x = (uint32_t)__bfloat16_as_ushort(lx) | ((uint32_t)__bfloat16_as_ushort(ly) << 16);
    l.y = (uint32_t)__bfloat16_as_ushort(lz) | ((uint32_t)__bfloat16_as_ushort(lw) << 16);
}

__global__ __launch_bounds__(256)
void convert_x(const float* __restrict__ x)
{
    size_t i = (size_t)blockIdx.x * 256 + threadIdx.x;   // float4 idx, < 4194304
    float4 v = ((const float4*)x)[i];
    uint2 h, l; split4_pack(v, h, l);
    *(uint2*)&g_xh[i * 4] = h;
    *(uint2*)&g_xl[i * 4] = l;
}

__global__ __launch_bounds__(256)
void convert_w(const float* __restrict__ Wq, const float* __restrict__ Wk,
               const float* __restrict__ Wv)
{
    int mat = blockIdx.y;
    const float* W = (mat == 0) ? Wq : ((mat == 1) ? Wk : Wv);
    size_t i = (size_t)blockIdx.x * 256 + threadIdx.x;   // float4 idx, < 16384
    float4 v = ((const float4*)W)[i];
    uint2 h, l; split4_pack(v, h, l);
    *(uint2*)&g_wh[(size_t)mat * 65536 + i * 4] = h;
    *(uint2*)&g_wl[(size_t)mat * 65536 + i * 4] = l;
}

// ---------------- SMEM layout: persistent A + 2-stage B ring ----------------
// A (W tile): 128 rows x 256 k bf16, row stride 528 B (512 + 16 pad) -> 67584/sel
// B (X tile): 64 k-rows x 128 n bf16, row stride 272 B -> 17408 per sel
#define A_STRIDE 528
#define OFF_AH   0
#define OFF_AL   67584
#define A_TOTAL  135168
#define B_STRIDE 272
#define B_SEL    17408
#define B_CHUNK  34816
#define OFF_B(st) (A_TOTAL + (st) * B_CHUNK)
#define GEMM_SMEM (A_TOTAL + 2 * B_CHUNK)   // 204800

// ============ persistent-A mma.sync QKV GEMM (cp.async bf16) ================
// grid: 144 CTAs = 12 combos (mat*4 + batch*2 + mtile) x 12 n-slices.
// CTA: A[mtile 128 rows, K=256] persistent; loops 21-22 ntiles x 4 k-chunks.
// 256 threads, 8 warps: warpM(4) x warpN(2); warp tile M=32(2 mf) x N=64.
__global__ __launch_bounds__(256, 1)
void qkv_gemm_mma(const float* __restrict__ bq, const float* __restrict__ bk,
                  const float* __restrict__ bv)
{
    extern __shared__ char sm[];
    const uint32_t smb = smem_u32(sm);

    const int tid   = threadIdx.x;
    const int warp  = tid >> 5, lane = tid & 31;
    const int warpM = warp >> 1, warpN = warp & 1;

    const int combo = blockIdx.x / 12;
    const int slice = blockIdx.x % 12;
    const int mat   = combo >> 2;
    const int bb    = (combo >> 1) & 1;
    const int mtile = combo & 1;
    const int ntbase = (slice < 4) ? slice * 22 : 88 + (slice - 4) * 21;
    const int njobs  = (slice < 4) ? 22 : 21;
    const int total  = njobs * 4;

    const float* bias = (mat == 0) ? bq : ((mat == 1) ? bk : bv);
    float* outp = ((mat == 0) ? g_q : ((mat == 1) ? g_k : g_v))
                  + (size_t)bb * CCH * SPAT;
    const __nv_bfloat16* Wh = g_wh + (size_t)mat * 65536 + (size_t)mtile * 128 * 256;
    const __nv_bfloat16* Wl = g_wl + (size_t)mat * 65536 + (size_t)mtile * 128 * 256;
    const __nv_bfloat16* Xh = g_xh + (size_t)bb * CCH * SPAT;
    const __nv_bfloat16* Xl = g_xl + (size_t)bb * CCH * SPAT;

    // ---- B chunk fetch: flat chunk index c -> (ntile, kchunk) into stage st
    auto issueB = [&](int c, int st) {
        const int nt  = ntbase + (c >> 2);
        const int kc0 = (c & 3) << 6;
        const int n0  = nt << 7;
        const uint32_t base = smb + OFF_B(st);
#pragma unroll
        for (int t = 0; t < 4; t++) {
            int idx = tid + t * 256;           // 0..1023
            int row = idx >> 4, piece = idx & 15;
            uint32_t doff = (uint32_t)row * B_STRIDE + piece * 16;
            size_t soff = (size_t)(kc0 + row) * SPAT + n0 + piece * 8;
            cp16(base + doff,         Xh + soff);
            cp16(base + B_SEL + doff, Xl + soff);
        }
    };

    // ---- persistent A load (once) ------------------------------------------
#pragma unroll
    for (int t = 0; t < 16; t++) {
        int idx = tid + t * 256;               // 0..4095
        int row = idx >> 5, piece = idx & 31;
        uint32_t doff = (uint32_t)row * A_STRIDE + piece * 16;
        size_t soff = (size_t)row * 256 + piece * 8;
        cp16(smb + OFF_AH + doff, Wh + soff);
        cp16(smb + OFF_AL + doff, Wl + soff);
    }
    issueB(0, 0); CP_COMMIT();    // group0: A + B0
    issueB(1, 1); CP_COMMIT();    // group1: B1

    float acc[2][8][4];

    const uint32_t a_rowb = (warpM * 32 + (lane & 15)) * A_STRIDE + (lane >> 4) * 16;
    const uint32_t b_col  = warpN * 128 + (lane >> 4) * 16;
    const uint32_t b_rowl = (lane & 15) * B_STRIDE;

#pragma unroll 1
    for (int c = 0; c < total; c++) {
        CP_WAIT(1);
        __syncthreads();

        if ((c & 3) == 0) {
#pragma unroll
            for (int i = 0; i < 2; i++)
#pragma unroll
                for (int j = 0; j < 8; j++)
#pragma unroll
                    for (int k = 0; k < 4; k++) acc[i][j][k] = 0.f;
        }

        const uint32_t bbuf = smb + OFF_B(c & 1);
        const uint32_t acol = (uint32_t)(c & 3) * 128;   // k-chunk col bytes in A

#pragma unroll
        for (int s = 0; s < 4; s++) {
            uint32_t bfr[4][2][4];
#pragma unroll
            for (int p = 0; p < 4; p++) {
                uint32_t base = bbuf + (uint32_t)(s * 16) * B_STRIDE + b_rowl
                              + b_col + p * 32;
                ldm_x4t(bfr[p][0], base);
                ldm_x4t(bfr[p][1], base + B_SEL);
            }
#pragma unroll
            for (int mf = 0; mf < 2; mf++) {
                uint32_t afr[2][4];
                uint32_t abase = smb + a_rowb + mf * (16 * A_STRIDE) + acol + s * 32;
                ldm_x4(afr[0], abase + OFF_AH);
                ldm_x4(afr[1], abase + OFF_AL);
#pragma unroll
                for (int p = 0; p < 4; p++)
#pragma unroll
                    for (int h = 0; h < 2; h++) {
                        float* cc = acc[mf][p * 2 + h];
                        mma_bf16(cc, afr[0], &bfr[p][0][h * 2]);   // Ah*Bh
                        mma_bf16(cc, afr[0], &bfr[p][1][h * 2]);   // Ah*Bl
                        mma_bf16(cc, afr[1], &bfr[p][0][h * 2]);   // Al*Bh
                    }
            }
        }
        __syncthreads();

        if (c + 2 < total) issueB(c + 2, c & 1);
        CP_COMMIT();   // one group per iteration keeps wait_group counting uniform

        if ((c & 3) == 3) {
            const int n0 = (ntbase + (c >> 2)) << 7;
#pragma unroll
            for (int mf = 0; mf < 2; mf++) {
                int mrow0 = mtile * 128 + warpM * 32 + mf * 16 + (lane >> 2);
                float b0 = bias[mrow0];
                float b1 = bias[mrow0 + 8];
                int ncol = n0 + warpN * 64 + (lane & 3) * 2;
#pragma unroll
                for (int nf = 0; nf < 8; nf++) {
                    float* cc = acc[mf][nf];
                    float2 v0 = make_float2(cc[0] + b0, cc[1] + b0);
                    float2 v1 = make_float2(cc[2] + b1, cc[3] + b1);
                    *(float2*)&outp[(size_t)mrow0 * SPAT + ncol + nf * 8]       = v0;
                    *(float2*)&outp[(size_t)(mrow0 + 8) * SPAT + ncol + nf * 8] = v1;
                }
            }
        }
    }
}

// ======== phase 1: softmax-attn*v -> w1+relu -> t[16], + sup prior ==========
// grid 512 blocks x 128 threads per branch; thread = one voxel.
template <int NSUP>
__global__ __launch_bounds__(128)
void attn_t_kernel(int br,
                   const float* __restrict__ w1,  const float* __restrict__ b1,
                   const float* __restrict__ wsup, const float* __restrict__ bsup,
                   float* __restrict__ sup_out)
{
    __shared__ float w1s[16 * 128];
    __shared__ float wss[NSUP * 128];
    __shared__ float b1s[16];
    __shared__ float bss[NSUP];

    const int ch_off = br << 7;
    int tid = threadIdx.x;
    for (int i = tid; i < 2048; i += 128) w1s[i] = w1[i];
    for (int i = tid; i < NSUP * 128; i += 128) wss[i] = wsup[i];
    if (tid < 16)   b1s[tid] = b1[tid];
    if (tid < NSUP) bss[tid] = bsup[tid];
    __syncthreads();

    int vg = blockIdx.x * 128 + tid;   // global voxel (b,s), < 65536
    int b  = vg >> 15;
    int s  = vg & (SPAT - 1);
    size_t base = (size_t)b * CCH * SPAT + (size_t)ch_off * SPAT + s;

    float tacc[16];
#pragma unroll
    for (int j = 0; j < 16; j++) tacc[j] = 0.f;
    float supacc[NSUP];
#pragma unroll
    for (int j = 0; j < NSUP; j++) supacc[j] = 0.f;

#pragma unroll 1
    for (int h = 0; h < 8; h++) {
        float qv[16], ev[16], vv[16];
#pragma unroll
        for (int i = 0; i < 16; i++) {
            size_t a = base + (size_t)(h * 16 + i) * SPAT;
            qv[i] = g_q[a];
            float kv = g_k[a];
            vv[i] = g_v[a];
            ev[i] = qv[i] * kv * 0.25f;   // SCALE = HD^-0.5 = 0.25
        }
        float m = ev[0];
#pragma unroll
        for (int i = 1; i < 16; i++) m = fmaxf(m, ev[i]);
        float ssum = 0.f;
#pragma unroll
        for (int i = 0; i < 16; i++) { ev[i] = __expf(ev[i] - m); ssum += ev[i]; }
        float inv = 1.f / ssum;
#pragma unroll
        for (int i = 0; i < 16; i++) {
            float o = ev[i] * inv * vv[i];
            int c = h * 16 + i;
#pragma unroll
            for (int j = 0; j < 16; j++) tacc[j] += w1s[j * 128 + c] * o;
#pragma unroll
            for (int j = 0; j < NSUP; j++) supacc[j] += wss[j * 128 + c] * qv[i];
        }
    }

    float* tp = &g_t[br * 1048576 + vg];
#pragma unroll
    for (int j = 0; j < 16; j++)
        tp[j * 65536] = fmaxf(tacc[j] + b1s[j], 0.f);

    size_t sbase = (size_t)b * NSUP * SPAT + s;
#pragma unroll
    for (int j = 0; j < NSUP; j++)
        sup_out[sbase + (size_t)j * SPAT] = supacc[j] + bss[j];
}

// ======== phase 2: out_s = sigmoid(W2 @ t + b2) =============================
// grid (256 chunks of 256 voxels, 2 branches), 128 threads; thread = 2 voxels.
__global__ __launch_bounds__(128)
void se2_kernel(const float* __restrict__ w2a, const float* __restrict__ b2a,
                const float* __restrict__ w2b, const float* __restrict__ b2b,
                float* __restrict__ out)
{
    __shared__ float ts[16 * 256];
    __shared__ float w2s[256 * 16];
    __shared__ float b2s[256];

    const int br = blockIdx.y;
    const float* w2 = br ? w2b : w2a;
    const float* b2 = br ? b2b : b2a;
    float* outp = out + (size_t)br * REG_SZ;

    const int tid = threadIdx.x;
    const int vg0 = blockIdx.x * 256;

#pragma unroll
    for (int t = 0; t < 32; t++) w2s[tid + t * 128] = w2[tid + t * 128];
    b2s[tid] = b2[tid];
    b2s[tid + 128] = b2[tid + 128];
    const float* tg = &g_t[br * 1048576 + vg0];
#pragma unroll
    for (int t = 0; t < 32; t++) {
        int idx = tid + t * 128;            // 0..4095
        ts[idx] = tg[(idx >> 8) * 65536 + (idx & 255)];
    }
    __syncthreads();

    float tv0[16], tv1[16];
#pragma unroll
    for (int j = 0; j < 16; j++) {
        tv0[j] = ts[j * 256 + tid];
        tv1[j] = ts[j * 256 + tid + 128];
    }

    const int vgA = vg0 + tid;
    const int bA = vgA >> 15, sA = vgA & (SPAT - 1);
    const int vgB = vg0 + tid + 128;
    const int bB = vgB >> 15, sB = vgB & (SPAT - 1);
    float* oA = outp + (size_t)bA * CCH * SPAT + sA;
    float* oB = outp + (size_t)bB * CCH * SPAT + sB;

#pragma unroll 8
    for (int o = 0; o < 256; o++) {
        const float* w = &w2s[o * 16];
        float a0 = b2s[o], a1 = b2s[o];
#pragma unroll
        for (int j = 0; j < 16; j++) {
            float wv = w[j];
            a0 += wv * tv0[j];
            a1 += wv * tv1[j];
        }
        oA[(size_t)o * SPAT] = 1.f / (1.f + __expf(-a0));
        oB[(size_t)o * SPAT] = 1.f / (1.f + __expf(-a1));
    }
}

// ---------------- deterministic max/mean/min pooling (float4) ---------------
__global__ __launch_bounds__(256)
void pool_kernel(const float* __restrict__ outbase)
{
    __shared__ float smx[256], smn[256], ssm[256];
    int blk = blockIdx.x;        // 0..1023 : region*512 + b*256 + c
    int r   = blk >> 9;
    int bc  = blk & 511;
    const float4* p = (const float4*)(outbase + (size_t)r * REG_SZ + (size_t)bc * SPAT);
    int tid = threadIdx.x;
    float mx = -1e30f, mn = 1e30f, sm = 0.f;
#pragma unroll 4
    for (int i = tid; i < SPAT / 4; i += 256) {
        float4 v = p[i];
        mx = fmaxf(mx, fmaxf(fmaxf(v.x, v.y), fmaxf(v.z, v.w)));
        mn = fminf(mn, fminf(fminf(v.x, v.y), fminf(v.z, v.w)));
        sm += (v.x + v.y) + (v.z + v.w);
    }
    smx[tid] = mx; smn[tid] = mn; ssm[tid] = sm;
    __syncthreads();
    for (int st = 128; st > 0; st >>= 1) {
        if (tid < st) {
            smx[tid] = fmaxf(smx[tid], smx[tid + st]);
            smn[tid] = fminf(smn[tid], smn[tid + st]);
            ssm[tid] += ssm[tid + st];
        }
        __syncthreads();
    }
    if (tid == 0) {
        g_pool[blk * 3 + 0] = smx[0];
        g_pool[blk * 3 + 1] = ssm[0] * (1.f / 32768.f);
        g_pool[blk * 3 + 2] = smn[0];
    }
}

// ---------------- gate: Conv1d(3->1) + FC squeeze-excite --------------------
__global__ __launch_bounds__(256)
void gate_kernel(const float* __restrict__ sq1w, const float* __restrict__ sq1b,
                 const float* __restrict__ sq2w, const float* __restrict__ sq2b,
                 const float* __restrict__ f1w1, const float* __restrict__ f1b1,
                 const float* __restrict__ f1w2, const float* __restrict__ f1b2,
                 const float* __restrict__ f2w1, const float* __restrict__ f2b1,
                 const float* __restrict__ f2w2, const float* __restrict__ f2b2)
{
    int r = blockIdx.x >> 1, b = blockIdx.x & 1;
    const float* sqw = r ? sq2w : sq1w;
    const float* sqb = r ? sq2b : sq1b;
    const float* fw1 = r ? f2w1 : f1w1;
    const float* fb1 = r ? f2b1 : f1b1;
    const float* fw2 = r ? f2w2 : f1w2;
    const float* fb2 = r ? f2b2 : f1b2;

    __shared__ float sqs[256], hs[16];
    int c = threadIdx.x;
    const float* pr = &g_pool[(r * 512 + b * 256 + c) * 3];
    sqs[c] = pr[0] * sqw[0] + pr[1] * sqw[1] + pr[2] * sqw[2] + sqb[0];
    __syncthreads();
    if (c < 16) {
        float a = fb1[c];
        for (int j = 0; j < 256; j++) a += fw1[c * 256 + j] * sqs[j];
        hs[c] = fmaxf(a, 0.f);
    }
    __syncthreads();
    float a = fb2[c];
#pragma unroll
    for (int j = 0; j < 16; j++) a += fw2[c * 16 + j] * hs[j];
    g_gate[r * 512 + b * 256 + c] = 1.f / (1.f + __expf(-a));
}

// ======== final: out = gate * sigmoid(W2 @ t + b2), recomputed from t =======
// grid (512, 2), 128 threads; thread = one voxel. Write-only 268MB.
__global__ __launch_bounds__(128)
void final_kernel(const float* __restrict__ w2a, const float* __restrict__ b2a,
                  const float* __restrict__ w2b, const float* __restrict__ b2b,
                  float* __restrict__ out)
{
    __shared__ float w2s[256 * 16];
    __shared__ float b2s[256];
    __shared__ float gs[256];

    const int br = blockIdx.y;
    const float* w2 = br ? w2b : w2a;
    const float* b2 = br ? b2b : b2a;
    float* outp = out + (size_t)br * REG_SZ;

    const int tid = threadIdx.x;
    const int vg0 = blockIdx.x * 128;
    const int b   = vg0 >> 15;            // constant per block

#pragma unroll
    for (int t = 0; t < 32; t++) w2s[tid + t * 128] = w2[tid + t * 128];
    b2s[tid] = b2[tid];
    b2s[tid + 128] = b2[tid + 128];
    gs[tid] = g_gate[br * 512 + b * 256 + tid];
    gs[tid + 128] = g_gate[br * 512 + b * 256 + tid + 128];

    const int vg = vg0 + tid;
    const int s  = vg & (SPAT - 1);
    float tv[16];
    const float* tg = &g_t[br * 1048576 + vg];
#pragma unroll
    for (int j = 0; j < 16; j++) tv[j] = tg[j * 65536];
    __syncthreads();

    float* op = outp + (size_t)b * CCH * SPAT + s;
#pragma unroll 8
    for (int o = 0; o < 256; o++) {
        const float* w = &w2s[o * 16];
        float a = b2s[o];
#pragma unroll
        for (int j = 0; j < 16; j++) a += w[j] * tv[j];
        op[(size_t)o * SPAT] = gs[o] / (1.f + __expf(-a));
    }
}

// ---------------- launch ----------------------------------------------------
extern "C" void kernel_launch(void* const* d_in, const int* in_sizes, int n_in,
                              void* d_out, int out_size)
{
    const float* x      = (const float*)d_in[0];
    const float* Wq     = (const float*)d_in[1];
    const float* bq     = (const float*)d_in[2];
    const float* Wk     = (const float*)d_in[3];
    const float* bk     = (const float*)d_in[4];
    const float* Wv     = (const float*)d_in[5];
    const float* bv     = (const float*)d_in[6];
    const float* Wq1p   = (const float*)d_in[7];
    const float* bq1p   = (const float*)d_in[8];
    const float* Wq2p   = (const float*)d_in[9];
    const float* bq2p   = (const float*)d_in[10];
    const float* sq1_w  = (const float*)d_in[11];
    const float* sq1_b  = (const float*)d_in[12];
    const float* sq2_w  = (const float*)d_in[13];
    const float* sq2_b  = (const float*)d_in[14];
    const float* se1_w1 = (const float*)d_in[15];
    const float* se1_b1 = (const float*)d_in[16];
    const float* se1_w2 = (const float*)d_in[17];
    const float* se1_b2 = (const float*)d_in[18];
    const float* se2_w1 = (const float*)d_in[19];
    const float* se2_b1 = (const float*)d_in[20];
    const float* se2_w2 = (const float*)d_in[21];
    const float* se2_b2 = (const float*)d_in[22];
    const float* sec1_w1 = (const float*)d_in[23];
    const float* sec1_b1 = (const float*)d_in[24];
    const float* sec1_w2 = (const float*)d_in[25];
    const float* sec1_b2 = (const float*)d_in[26];
    const float* sec2_w1 = (const float*)d_in[27];
    const float* sec2_b1 = (const float*)d_in[28];
    const float* sec2_w2 = (const float*)d_in[29];
    const float* sec2_b2 = (const float*)d_in[30];

    float* out  = (float*)d_out;
    float* sup1 = out + (size_t)2 * REG_SZ;        // 33554432
    float* sup2 = sup1 + 2 * 6 * SPAT;             // 33947648

    convert_x<<<16384, 256>>>(x);
    dim3 gw(64, 3);
    convert_w<<<gw, 256>>>(Wq, Wk, Wv);

    cudaFuncSetAttribute(qkv_gemm_mma, cudaFuncAttributeMaxDynamicSharedMemorySize,
                         GEMM_SMEM);
    qkv_gemm_mma<<<144, 256, GEMM_SMEM>>>(bq, bk, bv);

    attn_t_kernel<6><<<512, 128>>>(0, se1_w1, se1_b1, Wq1p, bq1p, sup1);
    attn_t_kernel<1><<<512, 128>>>(1, se2_w1, se2_b1, Wq2p, bq2p, sup2);

    dim3 gs(256, 2);
    se2_kernel<<<gs, 128>>>(se1_w2, se1_b2, se2_w2, se2_b2, out);

    pool_kernel<<<1024, 256>>>(out);

    gate_kernel<<<4, 256>>>(sq1_w, sq1_b, sq2_w, sq2_b,
                            sec1_w1, sec1_b1, sec1_w2, sec1_b2,
                            sec2_w1, sec2_b1, sec2_w2, sec2_b2);

    dim3 gf(512, 2);
    final_kernel<<<gf, 128>>>(se1_w2, se1_b2, se2_w2, se2_b2, out);
}

// round 8
// speedup vs baseline: 2.1627x; 1.1046x over previous
#include <cuda_runtime.h>
#include <cuda_bf16.h>
#include <math.h>
#include <stdint.h>

#define SPAT 32768           // D*H*W
#define CCH  256             // channels
#define REG_SZ (2*256*32768) // one region (b, 256, 32768)

// ---------------- scratch (device globals; no allocations allowed) ----------
__device__ float g_q[REG_SZ];
__device__ float g_k[REG_SZ];
__device__ float g_v[REG_SZ];
__device__ float g_t[2 * 16 * 65536];       // [branch][j][b*32768+s]
__device__ __nv_bfloat16 g_xh[REG_SZ];      // x hi bf16
__device__ __nv_bfloat16 g_xl[REG_SZ];      // x lo bf16
__device__ __nv_bfloat16 g_wh[3 * 256 * 256];
__device__ __nv_bfloat16 g_wl[3 * 256 * 256];
__device__ float g_ppart[2 * 256 * 256 * 3];  // [br][chunk][c][max,sum,min]
__device__ float g_pool[2 * 512 * 3];   // [region][b*256+c][max,avg,min]
__device__ float g_gate[2 * 512];       // [region][b*256+c]

// ======================= helpers ============================================
__device__ __forceinline__ uint32_t smem_u32(const void* p) {
    uint32_t a;
    asm("{ .reg .u64 t; cvta.to.shared.u64 t, %1; cvt.u32.u64 %0, t; }"
        : "=r"(a) : "l"(p));
    return a;
}
__device__ __forceinline__ void cp16(uint32_t dst, const void* src) {
    asm volatile("cp.async.cg.shared.global [%0], [%1], 16;"
                 :: "r"(dst), "l"(src) : "memory");
}
#define CP_COMMIT() asm volatile("cp.async.commit_group;" ::: "memory")
#define CP_WAIT(n)  asm volatile("cp.async.wait_group %0;" :: "n"(n) : "memory")

__device__ __forceinline__ void ldm_x4(uint32_t* r, uint32_t a) {
    asm volatile("ldmatrix.sync.aligned.m8n8.x4.shared.b16 {%0,%1,%2,%3}, [%4];"
        : "=r"(r[0]), "=r"(r[1]), "=r"(r[2]), "=r"(r[3]) : "r"(a));
}
__device__ __forceinline__ void ldm_x4t(uint32_t* r, uint32_t a) {
    asm volatile("ldmatrix.sync.aligned.m8n8.x4.trans.shared.b16 {%0,%1,%2,%3}, [%4];"
        : "=r"(r[0]), "=r"(r[1]), "=r"(r[2]), "=r"(r[3]) : "r"(a));
}
__device__ __forceinline__ void mma_bf16(float* c, const uint32_t* a, const uint32_t* b) {
    asm volatile(
        "mma.sync.aligned.m16n8k16.row.col.f32.bf16.bf16.f32 "
        "{%0,%1,%2,%3}, {%4,%5,%6,%7}, {%8,%9}, {%0,%1,%2,%3};"
        : "+f"(c[0]), "+f"(c[1]), "+f"(c[2]), "+f"(c[3])
        : "r"(a[0]), "r"(a[1]), "r"(a[2]), "r"(a[3]), "r"(b[0]), "r"(b[1]));
}

// fast sigmoid: 0.5 + 0.5 * tanh(a/2)  (1 MUFU instead of ex2 + rcp)
__device__ __forceinline__ float sigm(float a) {
    float y;
    asm("tanh.approx.f32 %0, %1;" : "=f"(y) : "f"(a * 0.5f));
    return fmaf(y, 0.5f, 0.5f);
}

// ---------------- pre-convert: fp32 -> bf16 hi/lo ---------------------------
__device__ __forceinline__ void split4_pack(float4 v, uint2& h, uint2& l) {
    __nv_bfloat16 hx = __float2bfloat16_rn(v.x), hy = __float2bfloat16_rn(v.y);
    __nv_bfloat16 hz = __float2bfloat16_rn(v.z), hw = __float2bfloat16_rn(v.w);
    __nv_bfloat16 lx = __float2bfloat16_rn(v.x - __bfloat162float(hx));
    __nv_bfloat16 ly = __float2bfloat16_rn(v.y - __bfloat162float(hy));
    __nv_bfloat16 lz = __float2bfloat16_rn(v.z - __bfloat162float(hz));
    __nv_bfloat16 lw = __float2bfloat16_rn(v.w - __bfloat162float(hw));
    h.x = (uint32_t)__bfloat16_as_ushort(hx) | ((uint32_t)__bfloat16_as_ushort(hy) << 16);
    h.y = (uint32_t)__bfloat16_as_ushort(hz) | ((uint32_t)__bfloat16_as_ushort(hw) << 16);
    l.x = (uint32_t)__bfloat16_as_ushort(lx) | ((uint32_t)__bfloat16_as_ushort(ly) << 16);
    l.y = (uint32_t)__bfloat16_as_ushort(lz) | ((uint32_t)__bfloat16_as_ushort(lw) << 16);
}

__global__ __launch_bounds__(256)
void convert_x(const float* __restrict__ x)
{
    size_t i = (size_t)blockIdx.x * 256 + threadIdx.x;   // float4 idx, < 4194304
    float4 v = ((const float4*)x)[i];
    uint2 h, l; split4_pack(v, h, l);
    *(uint2*)&g_xh[i * 4] = h;
    *(uint2*)&g_xl[i * 4] = l;
}

__global__ __launch_bounds__(256)
void convert_w(const float* __restrict__ Wq, const float* __restrict__ Wk,
               const float* __restrict__ Wv)
{
    int mat = blockIdx.y;
    const float* W = (mat == 0) ? Wq : ((mat == 1) ? Wk : Wv);
    size_t i = (size_t)blockIdx.x * 256 + threadIdx.x;   // float4 idx, < 16384
    float4 v = ((const float4*)W)[i];
    uint2 h, l; split4_pack(v, h, l);
    *(uint2*)&g_wh[(size_t)mat * 65536 + i * 4] = h;
    *(uint2*)&g_wl[(size_t)mat * 65536 + i * 4] = l;
}

// ---------------- SMEM layout: persistent A + 2-stage B ring ----------------
#define A_STRIDE 528
#define OFF_AH   0
#define OFF_AL   67584
#define A_TOTAL  135168
#define B_STRIDE 272
#define B_SEL    17408
#define B_CHUNK  34816
#define OFF_B(st) (A_TOTAL + (st) * B_CHUNK)
#define GEMM_SMEM (A_TOTAL + 2 * B_CHUNK)   // 204800

// ============ persistent-A mma.sync QKV GEMM (cp.async bf16) ================
__global__ __launch_bounds__(256, 1)
void qkv_gemm_mma(const float* __restrict__ bq, const float* __restrict__ bk,
                  const float* __restrict__ bv)
{
    extern __shared__ char sm[];
    const uint32_t smb = smem_u32(sm);

    const int tid   = threadIdx.x;
    const int warp  = tid >> 5, lane = tid & 31;
    const int warpM = warp >> 1, warpN = warp & 1;

    const int combo = blockIdx.x / 12;
    const int slice = blockIdx.x % 12;
    const int mat   = combo >> 2;
    const int bb    = (combo >> 1) & 1;
    const int mtile = combo & 1;
    const int ntbase = (slice < 4) ? slice * 22 : 88 + (slice - 4) * 21;
    const int njobs  = (slice < 4) ? 22 : 21;
    const int total  = njobs * 4;

    const float* bias = (mat == 0) ? bq : ((mat == 1) ? bk : bv);
    float* outp = ((mat == 0) ? g_q : ((mat == 1) ? g_k : g_v))
                  + (size_t)bb * CCH * SPAT;
    const __nv_bfloat16* Wh = g_wh + (size_t)mat * 65536 + (size_t)mtile * 128 * 256;
    const __nv_bfloat16* Wl = g_wl + (size_t)mat * 65536 + (size_t)mtile * 128 * 256;
    const __nv_bfloat16* Xh = g_xh + (size_t)bb * CCH * SPAT;
    const __nv_bfloat16* Xl = g_xl + (size_t)bb * CCH * SPAT;

    auto issueB = [&](int c, int st) {
        const int nt  = ntbase + (c >> 2);
        const int kc0 = (c & 3) << 6;
        const int n0  = nt << 7;
        const uint32_t base = smb + OFF_B(st);
#pragma unroll
        for (int t = 0; t < 4; t++) {
            int idx = tid + t * 256;
            int row = idx >> 4, piece = idx & 15;
            uint32_t doff = (uint32_t)row * B_STRIDE + piece * 16;
            size_t soff = (size_t)(kc0 + row) * SPAT + n0 + piece * 8;
            cp16(base + doff,         Xh + soff);
            cp16(base + B_SEL + doff, Xl + soff);
        }
    };

#pragma unroll
    for (int t = 0; t < 16; t++) {
        int idx = tid + t * 256;
        int row = idx >> 5, piece = idx & 31;
        uint32_t doff = (uint32_t)row * A_STRIDE + piece * 16;
        size_t soff = (size_t)row * 256 + piece * 8;
        cp16(smb + OFF_AH + doff, Wh + soff);
        cp16(smb + OFF_AL + doff, Wl + soff);
    }
    issueB(0, 0); CP_COMMIT();
    issueB(1, 1); CP_COMMIT();

    float acc[2][8][4];

    const uint32_t a_rowb = (warpM * 32 + (lane & 15)) * A_STRIDE + (lane >> 4) * 16;
    const uint32_t b_col  = warpN * 128 + (lane >> 4) * 16;
    const uint32_t b_rowl = (lane & 15) * B_STRIDE;

#pragma unroll 1
    for (int c = 0; c < total; c++) {
        CP_WAIT(1);
        __syncthreads();

        if ((c & 3) == 0) {
#pragma unroll
            for (int i = 0; i < 2; i++)
#pragma unroll
                for (int j = 0; j < 8; j++)
#pragma unroll
                    for (int k = 0; k < 4; k++) acc[i][j][k] = 0.f;
        }

        const uint32_t bbuf = smb + OFF_B(c & 1);
        const uint32_t acol = (uint32_t)(c & 3) * 128;

#pragma unroll
        for (int s = 0; s < 4; s++) {
            uint32_t bfr[4][2][4];
#pragma unroll
            for (int p = 0; p < 4; p++) {
                uint32_t base = bbuf + (uint32_t)(s * 16) * B_STRIDE + b_rowl
                              + b_col + p * 32;
                ldm_x4t(bfr[p][0], base);
                ldm_x4t(bfr[p][1], base + B_SEL);
            }
#pragma unroll
            for (int mf = 0; mf < 2; mf++) {
                uint32_t afr[2][4];
                uint32_t abase = smb + a_rowb + mf * (16 * A_STRIDE) + acol + s * 32;
                ldm_x4(afr[0], abase + OFF_AH);
                ldm_x4(afr[1], abase + OFF_AL);
#pragma unroll
                for (int p = 0; p < 4; p++)
#pragma unroll
                    for (int h = 0; h < 2; h++) {
                        float* cc = acc[mf][p * 2 + h];
                        mma_bf16(cc, afr[0], &bfr[p][0][h * 2]);   // Ah*Bh
                        mma_bf16(cc, afr[0], &bfr[p][1][h * 2]);   // Ah*Bl
                        mma_bf16(cc, afr[1], &bfr[p][0][h * 2]);   // Al*Bh
                    }
            }
        }
        __syncthreads();

        if (c + 2 < total) issueB(c + 2, c & 1);
        CP_COMMIT();

        if ((c & 3) == 3) {
            const int n0 = (ntbase + (c >> 2)) << 7;
#pragma unroll
            for (int mf = 0; mf < 2; mf++) {
                int mrow0 = mtile * 128 + warpM * 32 + mf * 16 + (lane >> 2);
                float b0 = bias[mrow0];
                float b1 = bias[mrow0 + 8];
                int ncol = n0 + warpN * 64 + (lane & 3) * 2;
#pragma unroll
                for (int nf = 0; nf < 8; nf++) {
                    float* cc = acc[mf][nf];
                    float2 v0 = make_float2(cc[0] + b0, cc[1] + b0);
                    float2 v1 = make_float2(cc[2] + b1, cc[3] + b1);
                    *(float2*)&outp[(size_t)mrow0 * SPAT + ncol + nf * 8]       = v0;
                    *(float2*)&outp[(size_t)(mrow0 + 8) * SPAT + ncol + nf * 8] = v1;
                }
            }
        }
    }
}

// ======== phase 1: softmax-attn*v -> w1+relu -> t[16], + sup prior ==========
template <int NSUP>
__global__ __launch_bounds__(128)
void attn_t_kernel(int br,
                   const float* __restrict__ w1,  const float* __restrict__ b1,
                   const float* __restrict__ wsup, const float* __restrict__ bsup,
                   float* __restrict__ sup_out)
{
    __shared__ float w1s[16 * 128];
    __shared__ float wss[NSUP * 128];
    __shared__ float b1s[16];
    __shared__ float bss[NSUP];

    const int ch_off = br << 7;
    int tid = threadIdx.x;
    for (int i = tid; i < 2048; i += 128) w1s[i] = w1[i];
    for (int i = tid; i < NSUP * 128; i += 128) wss[i] = wsup[i];
    if (tid < 16)   b1s[tid] = b1[tid];
    if (tid < NSUP) bss[tid] = bsup[tid];
    __syncthreads();

    int vg = blockIdx.x * 128 + tid;   // global voxel (b,s), < 65536
    int b  = vg >> 15;
    int s  = vg & (SPAT - 1);
    size_t base = (size_t)b * CCH * SPAT + (size_t)ch_off * SPAT + s;

    float tacc[16];
#pragma unroll
    for (int j = 0; j < 16; j++) tacc[j] = 0.f;
    float supacc[NSUP];
#pragma unroll
    for (int j = 0; j < NSUP; j++) supacc[j] = 0.f;

#pragma unroll 1
    for (int h = 0; h < 8; h++) {
        float qv[16], ev[16], vv[16];
#pragma unroll
        for (int i = 0; i < 16; i++) {
            size_t a = base + (size_t)(h * 16 + i) * SPAT;
            qv[i] = g_q[a];
            float kv = g_k[a];
            vv[i] = g_v[a];
            ev[i] = qv[i] * kv * 0.25f;   // SCALE = HD^-0.5 = 0.25
        }
        float m = ev[0];
#pragma unroll
        for (int i = 1; i < 16; i++) m = fmaxf(m, ev[i]);
        float ssum = 0.f;
#pragma unroll
        for (int i = 0; i < 16; i++) { ev[i] = __expf(ev[i] - m); ssum += ev[i]; }
        float inv = 1.f / ssum;
#pragma unroll
        for (int i = 0; i < 16; i++) {
            float o = ev[i] * inv * vv[i];
            int c = h * 16 + i;
#pragma unroll
            for (int j = 0; j < 16; j++) tacc[j] += w1s[j * 128 + c] * o;
#pragma unroll
            for (int j = 0; j < NSUP; j++) supacc[j] += wss[j * 128 + c] * qv[i];
        }
    }

    float* tp = &g_t[br * 1048576 + vg];
#pragma unroll
    for (int j = 0; j < 16; j++)
        tp[j * 65536] = fmaxf(tacc[j] + b1s[j], 0.f);

    size_t sbase = (size_t)b * NSUP * SPAT + s;
#pragma unroll
    for (int j = 0; j < NSUP; j++)
        sup_out[sbase + (size_t)j * SPAT] = supacc[j] + bss[j];
}

// ======== fused se2 + pooling: partial max/sum/min of sigmoid(W2 t + b2) ====
// grid (256 chunks, 2 branches), 256 threads; thread = one output channel,
// iterates its chunk's 256 voxels. out_s is NOT stored (final recomputes).
__global__ __launch_bounds__(256)
void se2_pool_kernel(const float* __restrict__ w2a, const float* __restrict__ b2a,
                     const float* __restrict__ w2b, const float* __restrict__ b2b)
{
    __shared__ float ts[256 * 20];   // [voxel][j] padded rows of 20 floats

    const int br = blockIdx.y;
    const float* w2 = br ? w2b : w2a;
    const float* b2 = br ? b2b : b2a;

    const int c   = threadIdx.x;
    const int vg0 = blockIdx.x * 256;

    // per-channel weights in registers
    float w[16];
#pragma unroll
    for (int k = 0; k < 4; k++) {
        float4 v = ((const float4*)w2)[c * 4 + k];
        w[k * 4 + 0] = v.x; w[k * 4 + 1] = v.y;
        w[k * 4 + 2] = v.z; w[k * 4 + 3] = v.w;
    }
    const float bc = b2[c];

    // load t chunk transposed: ts[v][j]
    const float* tg = &g_t[br * 1048576 + vg0];
#pragma unroll
    for (int j = 0; j < 16; j++)
        ts[c * 20 + j] = tg[j * 65536 + c];
    __syncthreads();

    float mx = -1e30f, mn = 1e30f, sm = 0.f;
#pragma unroll 4
    for (int v = 0; v < 256; v++) {
        const float4* t4 = (const float4*)&ts[v * 20];
        float4 t0 = t4[0], t1 = t4[1], t2 = t4[2], t3 = t4[3];
        float a = bc;
        a += w[0] * t0.x;  a += w[1] * t0.y;  a += w[2] * t0.z;  a += w[3] * t0.w;
        a += w[4] * t1.x;  a += w[5] * t1.y;  a += w[6] * t1.z;  a += w[7] * t1.w;
        a += w[8] * t2.x;  a += w[9] * t2.y;  a += w[10] * t2.z; a += w[11] * t2.w;
        a += w[12] * t3.x; a += w[13] * t3.y; a += w[14] * t3.z; a += w[15] * t3.w;
        float sg = sigm(a);
        mx = fmaxf(mx, sg); mn = fminf(mn, sg); sm += sg;
    }

    float* pp = &g_ppart[((br * 256 + blockIdx.x) * 256 + c) * 3];
    pp[0] = mx; pp[1] = sm; pp[2] = mn;
}

// ======== reduce partials -> g_pool (fixed order, deterministic) ============
__global__ __launch_bounds__(256)
void reduce_pool_kernel()
{
    int tid = blockIdx.x * 256 + threadIdx.x;   // 0..1023 = r*512 + b*256 + c
    int r = tid >> 9, bc = tid & 511;
    int b = bc >> 8, c = bc & 255;
    float mx = -1e30f, mn = 1e30f, sm = 0.f;
    for (int k = 0; k < 128; k++) {
        const float* pp = &g_ppart[((r * 256 + b * 128 + k) * 256 + c) * 3];
        mx = fmaxf(mx, pp[0]); sm += pp[1]; mn = fminf(mn, pp[2]);
    }
    g_pool[tid * 3 + 0] = mx;
    g_pool[tid * 3 + 1] = sm * (1.f / 32768.f);
    g_pool[tid * 3 + 2] = mn;
}

// ---------------- gate: Conv1d(3->1) + FC squeeze-excite --------------------
__global__ __launch_bounds__(256)
void gate_kernel(const float* __restrict__ sq1w, const float* __restrict__ sq1b,
                 const float* __restrict__ sq2w, const float* __restrict__ sq2b,
                 const float* __restrict__ f1w1, const float* __restrict__ f1b1,
                 const float* __restrict__ f1w2, const float* __restrict__ f1b2,
                 const float* __restrict__ f2w1, const float* __restrict__ f2b1,
                 const float* __restrict__ f2w2, const float* __restrict__ f2b2)
{
    int r = blockIdx.x >> 1, b = blockIdx.x & 1;
    const float* sqw = r ? sq2w : sq1w;
    const float* sqb = r ? sq2b : sq1b;
    const float* fw1 = r ? f2w1 : f1w1;
    const float* fb1 = r ? f2b1 : f1b1;
    const float* fw2 = r ? f2w2 : f1w2;
    const float* fb2 = r ? f2b2 : f1b2;

    __shared__ float sqs[256], hs[16];
    int c = threadIdx.x;
    const float* pr = &g_pool[(r * 512 + b * 256 + c) * 3];
    sqs[c] = pr[0] * sqw[0] + pr[1] * sqw[1] + pr[2] * sqw[2] + sqb[0];
    __syncthreads();
    if (c < 16) {
        float a = fb1[c];
        for (int j = 0; j < 256; j++) a += fw1[c * 256 + j] * sqs[j];
        hs[c] = fmaxf(a, 0.f);
    }
    __syncthreads();
    float a = fb2[c];
#pragma unroll
    for (int j = 0; j < 16; j++) a += fw2[c * 16 + j] * hs[j];
    g_gate[r * 512 + b * 256 + c] = 1.f / (1.f + __expf(-a));
}

// ======== final: out = gate * sigmoid(W2 @ t + b2), recomputed from t =======
__global__ __launch_bounds__(128)
void final_kernel(const float* __restrict__ w2a, const float* __restrict__ b2a,
                  const float* __restrict__ w2b, const float* __restrict__ b2b,
                  float* __restrict__ out)
{
    __shared__ float w2s[256 * 16];
    __shared__ float b2s[256];
    __shared__ float gs[256];

    const int br = blockIdx.y;
    const float* w2 = br ? w2b : w2a;
    const float* b2 = br ? b2b : b2a;
    float* outp = out + (size_t)br * REG_SZ;

    const int tid = threadIdx.x;
    const int vg0 = blockIdx.x * 128;
    const int b   = vg0 >> 15;            // constant per block

#pragma unroll
    for (int t = 0; t < 32; t++) w2s[tid + t * 128] = w2[tid + t * 128];
    b2s[tid] = b2[tid];
    b2s[tid + 128] = b2[tid + 128];
    gs[tid] = g_gate[br * 512 + b * 256 + tid];
    gs[tid + 128] = g_gate[br * 512 + b * 256 + tid + 128];

    const int vg = vg0 + tid;
    const int s  = vg & (SPAT - 1);
    float tv[16];
    const float* tg = &g_t[br * 1048576 + vg];
#pragma unroll
    for (int j = 0; j < 16; j++) tv[j] = tg[j * 65536];
    __syncthreads();

    float* op = outp + (size_t)b * CCH * SPAT + s;
#pragma unroll 8
    for (int o = 0; o < 256; o++) {
        const float* w = &w2s[o * 16];
        float a = b2s[o];
#pragma unroll
        for (int j = 0; j < 16; j++) a += w[j] * tv[j];
        op[(size_t)o * SPAT] = gs[o] * sigm(a);
    }
}

// ---------------- launch ----------------------------------------------------
extern "C" void kernel_launch(void* const* d_in, const int* in_sizes, int n_in,
                              void* d_out, int out_size)
{
    const float* x      = (const float*)d_in[0];
    const float* Wq     = (const float*)d_in[1];
    const float* bq     = (const float*)d_in[2];
    const float* Wk     = (const float*)d_in[3];
    const float* bk     = (const float*)d_in[4];
    const float* Wv     = (const float*)d_in[5];
    const float* bv     = (const float*)d_in[6];
    const float* Wq1p   = (const float*)d_in[7];
    const float* bq1p   = (const float*)d_in[8];
    const float* Wq2p   = (const float*)d_in[9];
    const float* bq2p   = (const float*)d_in[10];
    const float* sq1_w  = (const float*)d_in[11];
    const float* sq1_b  = (const float*)d_in[12];
    const float* sq2_w  = (const float*)d_in[13];
    const float* sq2_b  = (const float*)d_in[14];
    const float* se1_w1 = (const float*)d_in[15];
    const float* se1_b1 = (const float*)d_in[16];
    const float* se1_w2 = (const float*)d_in[17];
    const float* se1_b2 = (const float*)d_in[18];
    const float* se2_w1 = (const float*)d_in[19];
    const float* se2_b1 = (const float*)d_in[20];
    const float* se2_w2 = (const float*)d_in[21];
    const float* se2_b2 = (const float*)d_in[22];
    const float* sec1_w1 = (const float*)d_in[23];
    const float* sec1_b1 = (const float*)d_in[24];
    const float* sec1_w2 = (const float*)d_in[25];
    const float* sec1_b2 = (const float*)d_in[26];
    const float* sec2_w1 = (const float*)d_in[27];
    const float* sec2_b1 = (const float*)d_in[28];
    const float* sec2_w2 = (const float*)d_in[29];
    const float* sec2_b2 = (const float*)d_in[30];

    float* out  = (float*)d_out;
    float* sup1 = out + (size_t)2 * REG_SZ;        // 33554432
    float* sup2 = sup1 + 2 * 6 * SPAT;             // 33947648

    convert_x<<<16384, 256>>>(x);
    dim3 gw(64, 3);
    convert_w<<<gw, 256>>>(Wq, Wk, Wv);

    cudaFuncSetAttribute(qkv_gemm_mma, cudaFuncAttributeMaxDynamicSharedMemorySize,
                         GEMM_SMEM);
    qkv_gemm_mma<<<144, 256, GEMM_SMEM>>>(bq, bk, bv);

    attn_t_kernel<6><<<512, 128>>>(0, se1_w1, se1_b1, Wq1p, bq1p, sup1);
    attn_t_kernel<1><<<512, 128>>>(1, se2_w1, se2_b1, Wq2p, bq2p, sup2);

    dim3 gp(256, 2);
    se2_pool_kernel<<<gp, 256>>>(se1_w2, se1_b2, se2_w2, se2_b2);

    reduce_pool_kernel<<<4, 256>>>();

    gate_kernel<<<4, 256>>>(sq1_w, sq1_b, sq2_w, sq2_b,
                            sec1_w1, sec1_b1, sec1_w2, sec1_b2,
                            sec2_w1, sec2_b1, sec2_w2, sec2_b2);

    dim3 gf(512, 2);
    final_kernel<<<gf, 128>>>(se1_w2, se1_b2, se2_w2, se2_b2, out);
}